// round 2
// baseline (speedup 1.0000x reference)
#include <cuda_runtime.h>
#include <cuda_bf16.h>
#include <cstdint>

// Problem constants (fixed by the reference)
#define MAXN 50000
#define DIMV 128
#define HEADS 4
#define CH 32
#define MAXE 800000
#define LRELU_SLOPE 0.2f
#define LN_EPS 1e-5f

// ---------------- scratch (device globals; no allocation allowed) ----------------
__device__ float g_hcat[MAXN * 256];    // [N][256]: h1 (0..127) | h2 (128..255)
__device__ float g_outcat[MAXN * 256];  // [N][256]: out1 | out2 (pre-bias accumulators)
__device__ float g_srcv[MAXN * 8];      // per-node src logits: es1[4] | es2[4]
__device__ float g_dstv[MAXN * 8];      // per-node dst logits: ed1[4] | ed2[4]
__device__ float g_s[MAXN * 8];         // segment exp-sums: s1[4] | s2[4]

__device__ __forceinline__ float lrelu(float v) { return v > 0.f ? v : LRELU_SLOPE * v; }

__device__ __forceinline__ void red_add_v4(float* p, float a, float b, float c, float d) {
    unsigned long long gp = (unsigned long long)__cvta_generic_to_global(p);
    asm volatile("red.global.add.v4.f32 [%0], {%1,%2,%3,%4};"
                 :: "l"(gp), "f"(a), "f"(b), "f"(c), "f"(d) : "memory");
}

// ---------------- kernel 0: zero accumulators ----------------
__global__ void zero_kernel(int n) {
    int i = blockIdx.x * blockDim.x + threadIdx.x;
    int n4 = n * 64;  // float4 slots in g_outcat
    if (i < n4) *(float4*)&g_outcat[i * 4] = make_float4(0.f, 0.f, 0.f, 0.f);
    if (i < n * 2) *(float4*)&g_s[i * 4] = make_float4(0.f, 0.f, 0.f, 0.f);
}

// ---------------- kernel 1: h = x @ [W1 | W2]  (fp32 tiled GEMM) ----------------
// Grid: (ceil(n/128), 2). blockIdx.y selects W1 (cols 0..127) or W2 (cols 128..255).
#define BM 128
#define BN 128
#define BK 32
__global__ __launch_bounds__(256) void gemm_kernel(const float* __restrict__ x,
                                                   const float* __restrict__ W1,
                                                   const float* __restrict__ W2, int n) {
    __shared__ float Xs[BK][BM + 4];
    __shared__ float Ws[BK][BN];
    int tid = threadIdx.x;
    int rowBase = blockIdx.x * BM;
    int colBase = blockIdx.y * BN;
    const float* W = (blockIdx.y == 0) ? W1 : W2;
    int tx = tid & 15, ty = tid >> 4;  // 16x16 thread grid, 8x8 micro-tile
    float acc[8][8];
#pragma unroll
    for (int i = 0; i < 8; i++)
#pragma unroll
        for (int j = 0; j < 8; j++) acc[i][j] = 0.f;

    for (int k0 = 0; k0 < DIMV; k0 += BK) {
        // load X tile 128x32 (transposed into smem)
#pragma unroll
        for (int i = 0; i < 4; i++) {
            int idx = tid + i * 256;   // float4 index, 0..1023
            int r = idx >> 3;          // row in tile
            int c4 = idx & 7;          // float4-col
            int grow = rowBase + r;
            float4 v = make_float4(0.f, 0.f, 0.f, 0.f);
            if (grow < n) v = *(const float4*)&x[grow * DIMV + k0 + c4 * 4];
            Xs[c4 * 4 + 0][r] = v.x; Xs[c4 * 4 + 1][r] = v.y;
            Xs[c4 * 4 + 2][r] = v.z; Xs[c4 * 4 + 3][r] = v.w;
        }
        // load W tile 32x128
#pragma unroll
        for (int i = 0; i < 4; i++) {
            int idx = tid + i * 256;   // float4 index
            int kr = idx >> 5;         // 32 f4 per row
            int c4 = idx & 31;
            *(float4*)&Ws[kr][c4 * 4] = *(const float4*)&W[(k0 + kr) * DIMV + c4 * 4];
        }
        __syncthreads();
#pragma unroll
        for (int kk = 0; kk < BK; kk++) {
            float a[8], b[8];
            *(float4*)&a[0] = *(const float4*)&Xs[kk][ty * 8];
            *(float4*)&a[4] = *(const float4*)&Xs[kk][ty * 8 + 4];
            *(float4*)&b[0] = *(const float4*)&Ws[kk][tx * 8];
            *(float4*)&b[4] = *(const float4*)&Ws[kk][tx * 8 + 4];
#pragma unroll
            for (int i = 0; i < 8; i++)
#pragma unroll
                for (int j = 0; j < 8; j++) acc[i][j] += a[i] * b[j];
        }
        __syncthreads();
    }
#pragma unroll
    for (int i = 0; i < 8; i++) {
        int grow = rowBase + ty * 8 + i;
        if (grow >= n) continue;
        *(float4*)&g_hcat[grow * 256 + colBase + tx * 8]     = make_float4(acc[i][0], acc[i][1], acc[i][2], acc[i][3]);
        *(float4*)&g_hcat[grow * 256 + colBase + tx * 8 + 4] = make_float4(acc[i][4], acc[i][5], acc[i][6], acc[i][7]);
    }
}

// ---------------- kernel 2: per-node attention logits (warp per node) ----------------
__global__ void logits_kernel(const float* __restrict__ as1, const float* __restrict__ ad1,
                              const float* __restrict__ as2, const float* __restrict__ ad2, int n) {
    int warp = (blockIdx.x * blockDim.x + threadIdx.x) >> 5;
    if (warp >= n) return;
    int lane = threadIdx.x & 31;
    int head = lane >> 3;
    int sub = lane & 7;
    float4 h1 = *(const float4*)&g_hcat[warp * 256 + lane * 4];
    float4 h2 = *(const float4*)&g_hcat[warp * 256 + 128 + lane * 4];
    float4 v_s1 = *(const float4*)&as1[head * CH + sub * 4];
    float4 v_d1 = *(const float4*)&ad1[head * CH + sub * 4];
    float4 v_s2 = *(const float4*)&as2[head * CH + sub * 4];
    float4 v_d2 = *(const float4*)&ad2[head * CH + sub * 4];
    float ps1 = h1.x * v_s1.x + h1.y * v_s1.y + h1.z * v_s1.z + h1.w * v_s1.w;
    float pd1 = h1.x * v_d1.x + h1.y * v_d1.y + h1.z * v_d1.z + h1.w * v_d1.w;
    float ps2 = h2.x * v_s2.x + h2.y * v_s2.y + h2.z * v_s2.z + h2.w * v_s2.w;
    float pd2 = h2.x * v_d2.x + h2.y * v_d2.y + h2.z * v_d2.z + h2.w * v_d2.w;
#pragma unroll
    for (int off = 4; off; off >>= 1) {
        ps1 += __shfl_down_sync(0xffffffffu, ps1, off);
        pd1 += __shfl_down_sync(0xffffffffu, pd1, off);
        ps2 += __shfl_down_sync(0xffffffffu, ps2, off);
        pd2 += __shfl_down_sync(0xffffffffu, pd2, off);
    }
    if (sub == 0) {
        g_srcv[warp * 8 + head] = ps1;
        g_srcv[warp * 8 + 4 + head] = ps2;
        g_dstv[warp * 8 + head] = pd1;
        g_dstv[warp * 8 + 4 + head] = pd2;
    }
}

// ---------------- kernel 3: segment exp-sum (thread per edge; m=0 shift) ----------------
__global__ void edge_sum_kernel(const int* __restrict__ ei, int E, int Etot) {
    int e = blockIdx.x * blockDim.x + threadIdx.x;
    if (e >= Etot) return;
    int s_, d_;
    if (e < E) { s_ = ei[e]; d_ = ei[E + e]; }
    else       { s_ = d_ = e - E; }
    float4 sv1 = *(const float4*)&g_srcv[s_ * 8];
    float4 sv2 = *(const float4*)&g_srcv[s_ * 8 + 4];
    float4 dv1 = *(const float4*)&g_dstv[d_ * 8];
    float4 dv2 = *(const float4*)&g_dstv[d_ * 8 + 4];
    float4 p1, p2;
    p1.x = __expf(lrelu(sv1.x + dv1.x)); p1.y = __expf(lrelu(sv1.y + dv1.y));
    p1.z = __expf(lrelu(sv1.z + dv1.z)); p1.w = __expf(lrelu(sv1.w + dv1.w));
    p2.x = __expf(lrelu(sv2.x + dv2.x)); p2.y = __expf(lrelu(sv2.y + dv2.y));
    p2.z = __expf(lrelu(sv2.z + dv2.z)); p2.w = __expf(lrelu(sv2.w + dv2.w));
    red_add_v4(&g_s[d_ * 8], p1.x, p1.y, p1.z, p1.w);
    red_add_v4(&g_s[d_ * 8 + 4], p2.x, p2.y, p2.z, p2.w);
}

// ---------------- kernel 4: weighted scatter aggregation (warp per edge) ----------------
__global__ void edge_agg_kernel(const int* __restrict__ ei, int E, int Etot) {
    int widx = (blockIdx.x * blockDim.x + threadIdx.x) >> 5;
    if (widx >= Etot) return;
    int lane = threadIdx.x & 31;
    int s_, d_;
    if (widx < E) { s_ = ei[widx]; d_ = ei[E + widx]; }
    else          { s_ = d_ = widx - E; }
    int head = lane >> 3;
    float es1 = g_srcv[s_ * 8 + head];
    float ed1 = g_dstv[d_ * 8 + head];
    float es2 = g_srcv[s_ * 8 + 4 + head];
    float ed2 = g_dstv[d_ * 8 + 4 + head];
    float a1 = __expf(lrelu(es1 + ed1)) / g_s[d_ * 8 + head];
    float a2 = __expf(lrelu(es2 + ed2)) / g_s[d_ * 8 + 4 + head];
    float4 h1 = *(const float4*)&g_hcat[s_ * 256 + lane * 4];
    float4 h2 = *(const float4*)&g_hcat[s_ * 256 + 128 + lane * 4];
    float* o = &g_outcat[d_ * 256 + lane * 4];
    red_add_v4(o,       h1.x * a1, h1.y * a1, h1.z * a1, h1.w * a1);
    red_add_v4(o + 128, h2.x * a2, h2.y * a2, h2.z * a2, h2.w * a2);
}

// ---------------- kernel 5: gate + combine + residual + LayerNorm (warp per node) ----------------
__global__ void finalize_kernel(const float* __restrict__ x,
                                const float* __restrict__ b1, const float* __restrict__ b2,
                                const float* __restrict__ gW, const float* __restrict__ gb,
                                const float* __restrict__ gamma, const float* __restrict__ beta,
                                float* __restrict__ out, int n) {
    int warp = (blockIdx.x * blockDim.x + threadIdx.x) >> 5;
    if (warp >= n) return;
    int lane = threadIdx.x & 31;
    int c0 = lane * 4;
    float4 o1 = *(const float4*)&g_outcat[warp * 256 + c0];
    float4 o2 = *(const float4*)&g_outcat[warp * 256 + 128 + c0];
    float4 bb1 = *(const float4*)&b1[c0];
    float4 bb2 = *(const float4*)&b2[c0];
    o1.x += bb1.x; o1.y += bb1.y; o1.z += bb1.z; o1.w += bb1.w;
    o2.x += bb2.x; o2.y += bb2.y; o2.z += bb2.z; o2.w += bb2.w;
    // gate logits: cat(out1,out2) @ gate_W[256,2]
    float g0 = 0.f, g1 = 0.f;
    {
        const float* w1r = &gW[c0 * 2];          // rows c0..c0+3
        const float* w2r = &gW[(128 + c0) * 2];  // rows 128+c0..
        g0 += o1.x * w1r[0] + o1.y * w1r[2] + o1.z * w1r[4] + o1.w * w1r[6];
        g1 += o1.x * w1r[1] + o1.y * w1r[3] + o1.z * w1r[5] + o1.w * w1r[7];
        g0 += o2.x * w2r[0] + o2.y * w2r[2] + o2.z * w2r[4] + o2.w * w2r[6];
        g1 += o2.x * w2r[1] + o2.y * w2r[3] + o2.z * w2r[5] + o2.w * w2r[7];
    }
#pragma unroll
    for (int off = 16; off; off >>= 1) {
        g0 += __shfl_xor_sync(0xffffffffu, g0, off);
        g1 += __shfl_xor_sync(0xffffffffu, g1, off);
    }
    g0 += gb[0]; g1 += gb[1];
    float mx = fmaxf(g0, g1);
    float e0 = __expf(g0 - mx), e1 = __expf(g1 - mx);
    float inv_se = 1.f / (e0 + e1);
    float w0 = e0 * inv_se, w1 = e1 * inv_se;

    float4 xv = *(const float4*)&x[warp * DIMV + c0];
    float4 y;
    y.x = xv.x + w0 * o1.x + w1 * o2.x;
    y.y = xv.y + w0 * o1.y + w1 * o2.y;
    y.z = xv.z + w0 * o1.z + w1 * o2.z;
    y.w = xv.w + w0 * o1.w + w1 * o2.w;
    float sum = y.x + y.y + y.z + y.w;
    float sq  = y.x * y.x + y.y * y.y + y.z * y.z + y.w * y.w;
#pragma unroll
    for (int off = 16; off; off >>= 1) {
        sum += __shfl_xor_sync(0xffffffffu, sum, off);
        sq  += __shfl_xor_sync(0xffffffffu, sq, off);
    }
    float mu = sum * (1.f / DIMV);
    float var = sq * (1.f / DIMV) - mu * mu;
    float inv = rsqrtf(var + LN_EPS);
    float4 gm = *(const float4*)&gamma[c0];
    float4 bt = *(const float4*)&beta[c0];
    float4 r;
    r.x = (y.x - mu) * inv * gm.x + bt.x;
    r.y = (y.y - mu) * inv * gm.y + bt.y;
    r.z = (y.z - mu) * inv * gm.z + bt.z;
    r.w = (y.w - mu) * inv * gm.w + bt.w;
    *(float4*)&out[warp * DIMV + c0] = r;
}

// ---------------- launch ----------------
extern "C" void kernel_launch(void* const* d_in, const int* in_sizes, int n_in,
                              void* d_out, int out_size) {
    const float* x   = (const float*)d_in[0];
    const int*   ei  = (const int*)d_in[1];
    const float* W1  = (const float*)d_in[2];
    const float* b1  = (const float*)d_in[3];
    const float* as1 = (const float*)d_in[4];
    const float* ad1 = (const float*)d_in[5];
    const float* W2  = (const float*)d_in[6];
    const float* b2  = (const float*)d_in[7];
    const float* as2 = (const float*)d_in[8];
    const float* ad2 = (const float*)d_in[9];
    const float* gW  = (const float*)d_in[10];
    const float* gb  = (const float*)d_in[11];
    const float* gam = (const float*)d_in[12];
    const float* bet = (const float*)d_in[13];
    float* out = (float*)d_out;

    int n = in_sizes[0] / DIMV;       // nodes
    int E = in_sizes[1] / 2;          // edges (before self-loops)
    int Etot = E + n;

    // 0) zero accumulators
    {
        int tot = n * 64;
        zero_kernel<<<(tot + 255) / 256, 256>>>(n);
    }
    // 1) h = x @ [W1 | W2]
    {
        dim3 grid((n + BM - 1) / BM, 2);
        gemm_kernel<<<grid, 256>>>(x, W1, W2, n);
    }
    // 2) per-node logits
    logits_kernel<<<(n * 32 + 255) / 256, 256>>>(as1, ad1, as2, ad2, n);
    // 3) segment exp-sums
    edge_sum_kernel<<<(Etot + 255) / 256, 256>>>(ei, E, Etot);
    // 4) weighted scatter aggregation
    {
        long long thr = (long long)Etot * 32;
        edge_agg_kernel<<<(int)((thr + 255) / 256), 256>>>(ei, E, Etot);
    }
    // 5) gate + combine + residual + LN
    finalize_kernel<<<(n * 32 + 255) / 256, 256>>>(x, b1, b2, gW, gb, gam, bet, out, n);
}

// round 3
// speedup vs baseline: 1.0008x; 1.0008x over previous
#include <cuda_runtime.h>
#include <cuda_bf16.h>
#include <cstdint>

// Problem constants (fixed by the reference)
#define MAXN 50000
#define DIMV 128
#define HEADS 4
#define CH 32
#define MAXE 800000
#define LRELU_SLOPE 0.2f
#define LN_EPS 1e-5f

// ---------------- scratch (device globals; no allocation allowed) ----------------
__device__ float g_hcat[MAXN * 256];    // [N][256]: h1 (0..127) | h2 (128..255)
__device__ float g_outcat[MAXN * 256];  // [N][256]: out1 | out2 (pre-bias accumulators)
__device__ float g_srcv[MAXN * 8];      // per-node src logits: es1[4] | es2[4]
__device__ float g_dstv[MAXN * 8];      // per-node dst logits: ed1[4] | ed2[4]
__device__ float g_s[MAXN * 8];         // segment exp-sums: s1[4] | s2[4]

__device__ __forceinline__ float lrelu(float v) { return v > 0.f ? v : LRELU_SLOPE * v; }

__device__ __forceinline__ void red_add_v4(float* p, float a, float b, float c, float d) {
    unsigned long long gp = (unsigned long long)__cvta_generic_to_global(p);
    asm volatile("red.global.add.v4.f32 [%0], {%1,%2,%3,%4};"
                 :: "l"(gp), "f"(a), "f"(b), "f"(c), "f"(d) : "memory");
}

// ---------------- kernel 0: zero accumulators ----------------
__global__ void zero_kernel(int n) {
    int i = blockIdx.x * blockDim.x + threadIdx.x;
    int n4 = n * 64;  // float4 slots in g_outcat
    if (i < n4) *(float4*)&g_outcat[i * 4] = make_float4(0.f, 0.f, 0.f, 0.f);
    if (i < n * 2) *(float4*)&g_s[i * 4] = make_float4(0.f, 0.f, 0.f, 0.f);
}

// ---------------- kernel 1: h = x @ [W1 | W2]  (fp32 tiled GEMM) ----------------
// Grid: (ceil(n/128), 2). blockIdx.y selects W1 (cols 0..127) or W2 (cols 128..255).
#define BM 128
#define BN 128
#define BK 32
__global__ __launch_bounds__(256) void gemm_kernel(const float* __restrict__ x,
                                                   const float* __restrict__ W1,
                                                   const float* __restrict__ W2, int n) {
    __shared__ float Xs[BK][BM + 4];
    __shared__ float Ws[BK][BN];
    int tid = threadIdx.x;
    int rowBase = blockIdx.x * BM;
    int colBase = blockIdx.y * BN;
    const float* W = (blockIdx.y == 0) ? W1 : W2;
    int tx = tid & 15, ty = tid >> 4;  // 16x16 thread grid, 8x8 micro-tile
    float acc[8][8];
#pragma unroll
    for (int i = 0; i < 8; i++)
#pragma unroll
        for (int j = 0; j < 8; j++) acc[i][j] = 0.f;

    for (int k0 = 0; k0 < DIMV; k0 += BK) {
        // load X tile 128x32 (transposed into smem)
#pragma unroll
        for (int i = 0; i < 4; i++) {
            int idx = tid + i * 256;   // float4 index, 0..1023
            int r = idx >> 3;          // row in tile
            int c4 = idx & 7;          // float4-col
            int grow = rowBase + r;
            float4 v = make_float4(0.f, 0.f, 0.f, 0.f);
            if (grow < n) v = *(const float4*)&x[grow * DIMV + k0 + c4 * 4];
            Xs[c4 * 4 + 0][r] = v.x; Xs[c4 * 4 + 1][r] = v.y;
            Xs[c4 * 4 + 2][r] = v.z; Xs[c4 * 4 + 3][r] = v.w;
        }
        // load W tile 32x128
#pragma unroll
        for (int i = 0; i < 4; i++) {
            int idx = tid + i * 256;   // float4 index
            int kr = idx >> 5;         // 32 f4 per row
            int c4 = idx & 31;
            *(float4*)&Ws[kr][c4 * 4] = *(const float4*)&W[(k0 + kr) * DIMV + c4 * 4];
        }
        __syncthreads();
#pragma unroll
        for (int kk = 0; kk < BK; kk++) {
            float a[8], b[8];
            *(float4*)&a[0] = *(const float4*)&Xs[kk][ty * 8];
            *(float4*)&a[4] = *(const float4*)&Xs[kk][ty * 8 + 4];
            *(float4*)&b[0] = *(const float4*)&Ws[kk][tx * 8];
            *(float4*)&b[4] = *(const float4*)&Ws[kk][tx * 8 + 4];
#pragma unroll
            for (int i = 0; i < 8; i++)
#pragma unroll
                for (int j = 0; j < 8; j++) acc[i][j] += a[i] * b[j];
        }
        __syncthreads();
    }
#pragma unroll
    for (int i = 0; i < 8; i++) {
        int grow = rowBase + ty * 8 + i;
        if (grow >= n) continue;
        *(float4*)&g_hcat[grow * 256 + colBase + tx * 8]     = make_float4(acc[i][0], acc[i][1], acc[i][2], acc[i][3]);
        *(float4*)&g_hcat[grow * 256 + colBase + tx * 8 + 4] = make_float4(acc[i][4], acc[i][5], acc[i][6], acc[i][7]);
    }
}

// ---------------- kernel 2: per-node attention logits (warp per node) ----------------
__global__ void logits_kernel(const float* __restrict__ as1, const float* __restrict__ ad1,
                              const float* __restrict__ as2, const float* __restrict__ ad2, int n) {
    int warp = (blockIdx.x * blockDim.x + threadIdx.x) >> 5;
    if (warp >= n) return;
    int lane = threadIdx.x & 31;
    int head = lane >> 3;
    int sub = lane & 7;
    float4 h1 = *(const float4*)&g_hcat[warp * 256 + lane * 4];
    float4 h2 = *(const float4*)&g_hcat[warp * 256 + 128 + lane * 4];
    float4 v_s1 = *(const float4*)&as1[head * CH + sub * 4];
    float4 v_d1 = *(const float4*)&ad1[head * CH + sub * 4];
    float4 v_s2 = *(const float4*)&as2[head * CH + sub * 4];
    float4 v_d2 = *(const float4*)&ad2[head * CH + sub * 4];
    float ps1 = h1.x * v_s1.x + h1.y * v_s1.y + h1.z * v_s1.z + h1.w * v_s1.w;
    float pd1 = h1.x * v_d1.x + h1.y * v_d1.y + h1.z * v_d1.z + h1.w * v_d1.w;
    float ps2 = h2.x * v_s2.x + h2.y * v_s2.y + h2.z * v_s2.z + h2.w * v_s2.w;
    float pd2 = h2.x * v_d2.x + h2.y * v_d2.y + h2.z * v_d2.z + h2.w * v_d2.w;
#pragma unroll
    for (int off = 4; off; off >>= 1) {
        ps1 += __shfl_down_sync(0xffffffffu, ps1, off);
        pd1 += __shfl_down_sync(0xffffffffu, pd1, off);
        ps2 += __shfl_down_sync(0xffffffffu, ps2, off);
        pd2 += __shfl_down_sync(0xffffffffu, pd2, off);
    }
    if (sub == 0) {
        g_srcv[warp * 8 + head] = ps1;
        g_srcv[warp * 8 + 4 + head] = ps2;
        g_dstv[warp * 8 + head] = pd1;
        g_dstv[warp * 8 + 4 + head] = pd2;
    }
}

// ---------------- kernel 3: segment exp-sum (thread per edge; m=0 shift) ----------------
__global__ void edge_sum_kernel(const int* __restrict__ ei, int E, int Etot) {
    int e = blockIdx.x * blockDim.x + threadIdx.x;
    if (e >= Etot) return;
    int s_, d_;
    if (e < E) { s_ = ei[e]; d_ = ei[E + e]; }
    else       { s_ = d_ = e - E; }
    float4 sv1 = *(const float4*)&g_srcv[s_ * 8];
    float4 sv2 = *(const float4*)&g_srcv[s_ * 8 + 4];
    float4 dv1 = *(const float4*)&g_dstv[d_ * 8];
    float4 dv2 = *(const float4*)&g_dstv[d_ * 8 + 4];
    float4 p1, p2;
    p1.x = __expf(lrelu(sv1.x + dv1.x)); p1.y = __expf(lrelu(sv1.y + dv1.y));
    p1.z = __expf(lrelu(sv1.z + dv1.z)); p1.w = __expf(lrelu(sv1.w + dv1.w));
    p2.x = __expf(lrelu(sv2.x + dv2.x)); p2.y = __expf(lrelu(sv2.y + dv2.y));
    p2.z = __expf(lrelu(sv2.z + dv2.z)); p2.w = __expf(lrelu(sv2.w + dv2.w));
    red_add_v4(&g_s[d_ * 8], p1.x, p1.y, p1.z, p1.w);
    red_add_v4(&g_s[d_ * 8 + 4], p2.x, p2.y, p2.z, p2.w);
}

// ---------------- kernel 4: weighted scatter aggregation (warp per edge) ----------------
__global__ void edge_agg_kernel(const int* __restrict__ ei, int E, int Etot) {
    int widx = (blockIdx.x * blockDim.x + threadIdx.x) >> 5;
    if (widx >= Etot) return;
    int lane = threadIdx.x & 31;
    int s_, d_;
    if (widx < E) { s_ = ei[widx]; d_ = ei[E + widx]; }
    else          { s_ = d_ = widx - E; }
    int head = lane >> 3;
    float es1 = g_srcv[s_ * 8 + head];
    float ed1 = g_dstv[d_ * 8 + head];
    float es2 = g_srcv[s_ * 8 + 4 + head];
    float ed2 = g_dstv[d_ * 8 + 4 + head];
    float a1 = __expf(lrelu(es1 + ed1)) / g_s[d_ * 8 + head];
    float a2 = __expf(lrelu(es2 + ed2)) / g_s[d_ * 8 + 4 + head];
    float4 h1 = *(const float4*)&g_hcat[s_ * 256 + lane * 4];
    float4 h2 = *(const float4*)&g_hcat[s_ * 256 + 128 + lane * 4];
    float* o = &g_outcat[d_ * 256 + lane * 4];
    red_add_v4(o,       h1.x * a1, h1.y * a1, h1.z * a1, h1.w * a1);
    red_add_v4(o + 128, h2.x * a2, h2.y * a2, h2.z * a2, h2.w * a2);
}

// ---------------- kernel 5: gate + combine + residual + LayerNorm (warp per node) ----------------
__global__ void finalize_kernel(const float* __restrict__ x,
                                const float* __restrict__ b1, const float* __restrict__ b2,
                                const float* __restrict__ gW, const float* __restrict__ gb,
                                const float* __restrict__ gamma, const float* __restrict__ beta,
                                float* __restrict__ out, int n) {
    int warp = (blockIdx.x * blockDim.x + threadIdx.x) >> 5;
    if (warp >= n) return;
    int lane = threadIdx.x & 31;
    int c0 = lane * 4;
    float4 o1 = *(const float4*)&g_outcat[warp * 256 + c0];
    float4 o2 = *(const float4*)&g_outcat[warp * 256 + 128 + c0];
    float4 bb1 = *(const float4*)&b1[c0];
    float4 bb2 = *(const float4*)&b2[c0];
    o1.x += bb1.x; o1.y += bb1.y; o1.z += bb1.z; o1.w += bb1.w;
    o2.x += bb2.x; o2.y += bb2.y; o2.z += bb2.z; o2.w += bb2.w;
    // gate logits: cat(out1,out2) @ gate_W[256,2]
    float g0 = 0.f, g1 = 0.f;
    {
        const float* w1r = &gW[c0 * 2];          // rows c0..c0+3
        const float* w2r = &gW[(128 + c0) * 2];  // rows 128+c0..
        g0 += o1.x * w1r[0] + o1.y * w1r[2] + o1.z * w1r[4] + o1.w * w1r[6];
        g1 += o1.x * w1r[1] + o1.y * w1r[3] + o1.z * w1r[5] + o1.w * w1r[7];
        g0 += o2.x * w2r[0] + o2.y * w2r[2] + o2.z * w2r[4] + o2.w * w2r[6];
        g1 += o2.x * w2r[1] + o2.y * w2r[3] + o2.z * w2r[5] + o2.w * w2r[7];
    }
#pragma unroll
    for (int off = 16; off; off >>= 1) {
        g0 += __shfl_xor_sync(0xffffffffu, g0, off);
        g1 += __shfl_xor_sync(0xffffffffu, g1, off);
    }
    g0 += gb[0]; g1 += gb[1];
    float mx = fmaxf(g0, g1);
    float e0 = __expf(g0 - mx), e1 = __expf(g1 - mx);
    float inv_se = 1.f / (e0 + e1);
    float w0 = e0 * inv_se, w1 = e1 * inv_se;

    float4 xv = *(const float4*)&x[warp * DIMV + c0];
    float4 y;
    y.x = xv.x + w0 * o1.x + w1 * o2.x;
    y.y = xv.y + w0 * o1.y + w1 * o2.y;
    y.z = xv.z + w0 * o1.z + w1 * o2.z;
    y.w = xv.w + w0 * o1.w + w1 * o2.w;
    float sum = y.x + y.y + y.z + y.w;
    float sq  = y.x * y.x + y.y * y.y + y.z * y.z + y.w * y.w;
#pragma unroll
    for (int off = 16; off; off >>= 1) {
        sum += __shfl_xor_sync(0xffffffffu, sum, off);
        sq  += __shfl_xor_sync(0xffffffffu, sq, off);
    }
    float mu = sum * (1.f / DIMV);
    float var = sq * (1.f / DIMV) - mu * mu;
    float inv = rsqrtf(var + LN_EPS);
    float4 gm = *(const float4*)&gamma[c0];
    float4 bt = *(const float4*)&beta[c0];
    float4 r;
    r.x = (y.x - mu) * inv * gm.x + bt.x;
    r.y = (y.y - mu) * inv * gm.y + bt.y;
    r.z = (y.z - mu) * inv * gm.z + bt.z;
    r.w = (y.w - mu) * inv * gm.w + bt.w;
    *(float4*)&out[warp * DIMV + c0] = r;
}

// ---------------- launch ----------------
extern "C" void kernel_launch(void* const* d_in, const int* in_sizes, int n_in,
                              void* d_out, int out_size) {
    const float* x   = (const float*)d_in[0];
    const int*   ei  = (const int*)d_in[1];
    const float* W1  = (const float*)d_in[2];
    const float* b1  = (const float*)d_in[3];
    const float* as1 = (const float*)d_in[4];
    const float* ad1 = (const float*)d_in[5];
    const float* W2  = (const float*)d_in[6];
    const float* b2  = (const float*)d_in[7];
    const float* as2 = (const float*)d_in[8];
    const float* ad2 = (const float*)d_in[9];
    const float* gW  = (const float*)d_in[10];
    const float* gb  = (const float*)d_in[11];
    const float* gam = (const float*)d_in[12];
    const float* bet = (const float*)d_in[13];
    float* out = (float*)d_out;

    int n = in_sizes[0] / DIMV;       // nodes
    int E = in_sizes[1] / 2;          // edges (before self-loops)
    int Etot = E + n;

    // 0) zero accumulators
    {
        int tot = n * 64;
        zero_kernel<<<(tot + 255) / 256, 256>>>(n);
    }
    // 1) h = x @ [W1 | W2]
    {
        dim3 grid((n + BM - 1) / BM, 2);
        gemm_kernel<<<grid, 256>>>(x, W1, W2, n);
    }
    // 2) per-node logits
    logits_kernel<<<(n * 32 + 255) / 256, 256>>>(as1, ad1, as2, ad2, n);
    // 3) segment exp-sums
    edge_sum_kernel<<<(Etot + 255) / 256, 256>>>(ei, E, Etot);
    // 4) weighted scatter aggregation
    {
        long long thr = (long long)Etot * 32;
        edge_agg_kernel<<<(int)((thr + 255) / 256), 256>>>(ei, E, Etot);
    }
    // 5) gate + combine + residual + LN
    finalize_kernel<<<(n * 32 + 255) / 256, 256>>>(x, b1, b2, gW, gb, gam, bet, out, n);
}

// round 4
// speedup vs baseline: 1.0668x; 1.0660x over previous
#include <cuda_runtime.h>
#include <cuda_bf16.h>
#include <cstdint>

// Problem constants (fixed by the reference)
#define MAXN 50000
#define DIMV 128
#define HEADS 4
#define CH 32
#define MAXE 800000
#define LRELU_SLOPE 0.2f
#define LN_EPS 1e-5f

// ---------------- scratch (device globals; no allocation allowed) ----------------
__device__ float g_hcat[MAXN * 256];        // [N][256]: h1 (0..127) | h2 (128..255)
__device__ float g_srcv[MAXN * 8];          // per-node src logits: es1[4] | es2[4]
__device__ float g_dstv[MAXN * 8];          // per-node dst logits: ed1[4] | ed2[4]
__device__ int   g_deg[MAXN];               // in-degree (incl self-loop)
__device__ int   g_off[MAXN + 1];           // CSR offsets
__device__ int   g_cursor[MAXN];            // scatter cursors
__device__ int   g_csr[MAXE + MAXN];        // CSR src indices (grouped by dst)

__device__ __forceinline__ float lrelu(float v) { return v > 0.f ? v : LRELU_SLOPE * v; }

__device__ __forceinline__ unsigned long long pack2(float x, float y) {
    unsigned long long r;
    asm("mov.b64 %0, {%1, %2};" : "=l"(r) : "f"(x), "f"(y));
    return r;
}
__device__ __forceinline__ void unpack2(unsigned long long v, float& x, float& y) {
    asm("mov.b64 {%0, %1}, %2;" : "=f"(x), "=f"(y) : "l"(v));
}
__device__ __forceinline__ void ffma2(unsigned long long& d, unsigned long long a, unsigned long long b) {
    asm("fma.rn.f32x2 %0, %1, %2, %0;" : "+l"(d) : "l"(a), "l"(b));
}

// ---------------- kernel 1: h = x @ [W1 | W2]  (fp32 tiled GEMM, f32x2 FFMA) ----------------
#define BM 128
#define BN 128
#define BK 32
__global__ __launch_bounds__(256) void gemm_kernel(const float* __restrict__ x,
                                                   const float* __restrict__ W1,
                                                   const float* __restrict__ W2, int n) {
    __shared__ __align__(16) float Xs[BK][BM + 4];
    __shared__ __align__(16) float Ws[BK][BN];
    int tid = threadIdx.x;
    int rowBase = blockIdx.x * BM;
    int colBase = blockIdx.y * BN;
    const float* W = (blockIdx.y == 0) ? W1 : W2;
    int tx = tid & 15, ty = tid >> 4;  // 16x16 thread grid, 8x8 micro-tile
    unsigned long long accp[8][4];
#pragma unroll
    for (int i = 0; i < 8; i++)
#pragma unroll
        for (int j = 0; j < 4; j++) accp[i][j] = 0ull;

    for (int k0 = 0; k0 < DIMV; k0 += BK) {
        // load X tile 128x32 (transposed into smem)
#pragma unroll
        for (int i = 0; i < 4; i++) {
            int idx = tid + i * 256;   // float4 index, 0..1023
            int r = idx >> 3;          // row in tile
            int c4 = idx & 7;          // float4-col
            int grow = rowBase + r;
            float4 v = make_float4(0.f, 0.f, 0.f, 0.f);
            if (grow < n) v = *(const float4*)&x[grow * DIMV + k0 + c4 * 4];
            Xs[c4 * 4 + 0][r] = v.x; Xs[c4 * 4 + 1][r] = v.y;
            Xs[c4 * 4 + 2][r] = v.z; Xs[c4 * 4 + 3][r] = v.w;
        }
        // load W tile 32x128
#pragma unroll
        for (int i = 0; i < 4; i++) {
            int idx = tid + i * 256;   // float4 index
            int kr = idx >> 5;         // 32 f4 per row
            int c4 = idx & 31;
            *(float4*)&Ws[kr][c4 * 4] = *(const float4*)&W[(k0 + kr) * DIMV + c4 * 4];
        }
        __syncthreads();
#pragma unroll
        for (int kk = 0; kk < BK; kk++) {
            float a[8];
            *(float4*)&a[0] = *(const float4*)&Xs[kk][ty * 8];
            *(float4*)&a[4] = *(const float4*)&Xs[kk][ty * 8 + 4];
            longlong2 b01 = *(const longlong2*)&Ws[kk][tx * 8];
            longlong2 b23 = *(const longlong2*)&Ws[kk][tx * 8 + 4];
            unsigned long long bp0 = (unsigned long long)b01.x;
            unsigned long long bp1 = (unsigned long long)b01.y;
            unsigned long long bp2 = (unsigned long long)b23.x;
            unsigned long long bp3 = (unsigned long long)b23.y;
#pragma unroll
            for (int i = 0; i < 8; i++) {
                unsigned long long ap = pack2(a[i], a[i]);
                ffma2(accp[i][0], ap, bp0);
                ffma2(accp[i][1], ap, bp1);
                ffma2(accp[i][2], ap, bp2);
                ffma2(accp[i][3], ap, bp3);
            }
        }
        __syncthreads();
    }
#pragma unroll
    for (int i = 0; i < 8; i++) {
        int grow = rowBase + ty * 8 + i;
        if (grow >= n) continue;
        float c0, c1, c2, c3, c4, c5, c6, c7;
        unpack2(accp[i][0], c0, c1);
        unpack2(accp[i][1], c2, c3);
        unpack2(accp[i][2], c4, c5);
        unpack2(accp[i][3], c6, c7);
        *(float4*)&g_hcat[grow * 256 + colBase + tx * 8]     = make_float4(c0, c1, c2, c3);
        *(float4*)&g_hcat[grow * 256 + colBase + tx * 8 + 4] = make_float4(c4, c5, c6, c7);
    }
}

// ---------------- kernel 2: per-node attention logits (warp per node) ----------------
__global__ void logits_kernel(const float* __restrict__ as1, const float* __restrict__ ad1,
                              const float* __restrict__ as2, const float* __restrict__ ad2, int n) {
    int warp = (blockIdx.x * blockDim.x + threadIdx.x) >> 5;
    if (warp >= n) return;
    int lane = threadIdx.x & 31;
    int head = lane >> 3;
    int sub = lane & 7;
    float4 h1 = *(const float4*)&g_hcat[warp * 256 + lane * 4];
    float4 h2 = *(const float4*)&g_hcat[warp * 256 + 128 + lane * 4];
    float4 v_s1 = *(const float4*)&as1[head * CH + sub * 4];
    float4 v_d1 = *(const float4*)&ad1[head * CH + sub * 4];
    float4 v_s2 = *(const float4*)&as2[head * CH + sub * 4];
    float4 v_d2 = *(const float4*)&ad2[head * CH + sub * 4];
    float ps1 = h1.x * v_s1.x + h1.y * v_s1.y + h1.z * v_s1.z + h1.w * v_s1.w;
    float pd1 = h1.x * v_d1.x + h1.y * v_d1.y + h1.z * v_d1.z + h1.w * v_d1.w;
    float ps2 = h2.x * v_s2.x + h2.y * v_s2.y + h2.z * v_s2.z + h2.w * v_s2.w;
    float pd2 = h2.x * v_d2.x + h2.y * v_d2.y + h2.z * v_d2.z + h2.w * v_d2.w;
#pragma unroll
    for (int off = 4; off; off >>= 1) {
        ps1 += __shfl_down_sync(0xffffffffu, ps1, off);
        pd1 += __shfl_down_sync(0xffffffffu, pd1, off);
        ps2 += __shfl_down_sync(0xffffffffu, ps2, off);
        pd2 += __shfl_down_sync(0xffffffffu, pd2, off);
    }
    if (sub == 0) {
        g_srcv[warp * 8 + head] = ps1;
        g_srcv[warp * 8 + 4 + head] = ps2;
        g_dstv[warp * 8 + head] = pd1;
        g_dstv[warp * 8 + 4 + head] = pd2;
    }
}

// ---------------- CSR build ----------------
__global__ void init_deg_kernel(int n) {
    int i = blockIdx.x * blockDim.x + threadIdx.x;
    if (i < n) g_deg[i] = 1;   // self-loop
}

__global__ void count_kernel(const int* __restrict__ ei, int E) {
    int e = blockIdx.x * blockDim.x + threadIdx.x;
    if (e < E) atomicAdd(&g_deg[ei[E + e]], 1);
}

// Single-block scan over g_deg -> g_off; also pre-places self-loop at off[i].
__global__ __launch_bounds__(1024) void scan_kernel(int n) {
    __shared__ int sm[1024];
    int t = threadIdx.x;
    int chunk = (n + 1023) / 1024;
    int start = t * chunk;
    int end = start + chunk; if (end > n) end = n;
    int s = 0;
    for (int i = start; i < end; i++) s += g_deg[i];
    sm[t] = s;
    __syncthreads();
#pragma unroll
    for (int off = 1; off < 1024; off <<= 1) {
        int v = (t >= off) ? sm[t - off] : 0;
        __syncthreads();
        sm[t] += v;
        __syncthreads();
    }
    int base = sm[t] - s;   // exclusive prefix
    for (int i = start; i < end; i++) {
        int d = g_deg[i];
        g_off[i] = base;
        g_csr[base] = i;            // self-loop first
        g_cursor[i] = base + 1;
        base += d;
    }
    if (t == 0) g_off[n] = sm[1023];
}

__global__ void scatter_kernel(const int* __restrict__ ei, int E) {
    int e = blockIdx.x * blockDim.x + threadIdx.x;
    if (e >= E) return;
    int src = ei[e];
    int dst = ei[E + e];
    int pos = atomicAdd(&g_cursor[dst], 1);
    g_csr[pos] = src;
}

// ---------------- kernel 3: CSR aggregation + gate + residual + LN (warp per node) ----------------
__global__ __launch_bounds__(256) void agg_finalize_kernel(
        const float* __restrict__ x,
        const float* __restrict__ b1, const float* __restrict__ b2,
        const float* __restrict__ gW, const float* __restrict__ gb,
        const float* __restrict__ gamma, const float* __restrict__ beta,
        float* __restrict__ out, int n) {
    int node = (blockIdx.x * blockDim.x + threadIdx.x) >> 5;
    if (node >= n) return;
    int lane = threadIdx.x & 31;
    int head = lane >> 3;
    int c0 = lane * 4;

    float ed1 = g_dstv[node * 8 + head];
    float ed2 = g_dstv[node * 8 + 4 + head];
    int beg = g_off[node];
    int end = g_off[node + 1];

    float4 num1 = make_float4(0.f, 0.f, 0.f, 0.f);
    float4 num2 = make_float4(0.f, 0.f, 0.f, 0.f);
    float den1 = 0.f, den2 = 0.f;

    for (int p = beg; p < end; p++) {
        int s = __ldg(&g_csr[p]);
        float es1 = __ldg(&g_srcv[s * 8 + head]);
        float es2 = __ldg(&g_srcv[s * 8 + 4 + head]);
        float4 h1 = *(const float4*)&g_hcat[s * 256 + c0];
        float4 h2 = *(const float4*)&g_hcat[s * 256 + 128 + c0];
        float p1 = __expf(lrelu(es1 + ed1));
        float p2 = __expf(lrelu(es2 + ed2));
        den1 += p1; den2 += p2;
        num1.x += p1 * h1.x; num1.y += p1 * h1.y; num1.z += p1 * h1.z; num1.w += p1 * h1.w;
        num2.x += p2 * h2.x; num2.y += p2 * h2.y; num2.z += p2 * h2.z; num2.w += p2 * h2.w;
    }

    float inv1 = 1.f / den1;
    float inv2 = 1.f / den2;
    float4 bb1 = *(const float4*)&b1[c0];
    float4 bb2 = *(const float4*)&b2[c0];
    float4 o1, o2;
    o1.x = num1.x * inv1 + bb1.x; o1.y = num1.y * inv1 + bb1.y;
    o1.z = num1.z * inv1 + bb1.z; o1.w = num1.w * inv1 + bb1.w;
    o2.x = num2.x * inv2 + bb2.x; o2.y = num2.y * inv2 + bb2.y;
    o2.z = num2.z * inv2 + bb2.z; o2.w = num2.w * inv2 + bb2.w;

    // gate logits: cat(out1,out2) @ gate_W[256,2]
    float g0 = 0.f, g1 = 0.f;
    {
        const float* w1r = &gW[c0 * 2];
        const float* w2r = &gW[(128 + c0) * 2];
        g0 += o1.x * w1r[0] + o1.y * w1r[2] + o1.z * w1r[4] + o1.w * w1r[6];
        g1 += o1.x * w1r[1] + o1.y * w1r[3] + o1.z * w1r[5] + o1.w * w1r[7];
        g0 += o2.x * w2r[0] + o2.y * w2r[2] + o2.z * w2r[4] + o2.w * w2r[6];
        g1 += o2.x * w2r[1] + o2.y * w2r[3] + o2.z * w2r[5] + o2.w * w2r[7];
    }
#pragma unroll
    for (int off = 16; off; off >>= 1) {
        g0 += __shfl_xor_sync(0xffffffffu, g0, off);
        g1 += __shfl_xor_sync(0xffffffffu, g1, off);
    }
    g0 += gb[0]; g1 += gb[1];
    float mx = fmaxf(g0, g1);
    float e0 = __expf(g0 - mx), e1 = __expf(g1 - mx);
    float inv_se = 1.f / (e0 + e1);
    float w0 = e0 * inv_se, w1 = e1 * inv_se;

    float4 xv = *(const float4*)&x[node * DIMV + c0];
    float4 y;
    y.x = xv.x + w0 * o1.x + w1 * o2.x;
    y.y = xv.y + w0 * o1.y + w1 * o2.y;
    y.z = xv.z + w0 * o1.z + w1 * o2.z;
    y.w = xv.w + w0 * o1.w + w1 * o2.w;
    float sum = y.x + y.y + y.z + y.w;
    float sq  = y.x * y.x + y.y * y.y + y.z * y.z + y.w * y.w;
#pragma unroll
    for (int off = 16; off; off >>= 1) {
        sum += __shfl_xor_sync(0xffffffffu, sum, off);
        sq  += __shfl_xor_sync(0xffffffffu, sq, off);
    }
    float mu = sum * (1.f / DIMV);
    float var = sq * (1.f / DIMV) - mu * mu;
    float inv = rsqrtf(var + LN_EPS);
    float4 gm = *(const float4*)&gamma[c0];
    float4 bt = *(const float4*)&beta[c0];
    float4 r;
    r.x = (y.x - mu) * inv * gm.x + bt.x;
    r.y = (y.y - mu) * inv * gm.y + bt.y;
    r.z = (y.z - mu) * inv * gm.z + bt.z;
    r.w = (y.w - mu) * inv * gm.w + bt.w;
    *(float4*)&out[node * DIMV + c0] = r;
}

// ---------------- launch ----------------
extern "C" void kernel_launch(void* const* d_in, const int* in_sizes, int n_in,
                              void* d_out, int out_size) {
    const float* x   = (const float*)d_in[0];
    const int*   ei  = (const int*)d_in[1];
    const float* W1  = (const float*)d_in[2];
    const float* b1  = (const float*)d_in[3];
    const float* as1 = (const float*)d_in[4];
    const float* ad1 = (const float*)d_in[5];
    const float* W2  = (const float*)d_in[6];
    const float* b2  = (const float*)d_in[7];
    const float* as2 = (const float*)d_in[8];
    const float* ad2 = (const float*)d_in[9];
    const float* gW  = (const float*)d_in[10];
    const float* gb  = (const float*)d_in[11];
    const float* gam = (const float*)d_in[12];
    const float* bet = (const float*)d_in[13];
    float* out = (float*)d_out;

    int n = in_sizes[0] / DIMV;       // nodes
    int E = in_sizes[1] / 2;          // edges (before self-loops)

    // 1) h = x @ [W1 | W2]
    {
        dim3 grid((n + BM - 1) / BM, 2);
        gemm_kernel<<<grid, 256>>>(x, W1, W2, n);
    }
    // 2) per-node logits
    logits_kernel<<<(n * 32 + 255) / 256, 256>>>(as1, ad1, as2, ad2, n);
    // 3) CSR build (dst-grouped)
    init_deg_kernel<<<(n + 255) / 256, 256>>>(n);
    count_kernel<<<(E + 255) / 256, 256>>>(ei, E);
    scan_kernel<<<1, 1024>>>(n);
    scatter_kernel<<<(E + 255) / 256, 256>>>(ei, E);
    // 4) register-accumulated aggregation + gate + residual + LN
    agg_finalize_kernel<<<(n * 32 + 255) / 256, 256>>>(x, b1, b2, gW, gb, gam, bet, out, n);
}

// round 6
// speedup vs baseline: 1.7009x; 1.5944x over previous
#include <cuda_runtime.h>
#include <cuda_bf16.h>
#include <cstdint>

// Problem constants (fixed by the reference)
#define MAXN 50000
#define DIMV 128
#define HEADS 4
#define CH 32
#define MAXE 800000
#define LRELU_SLOPE 0.2f
#define LN_EPS 1e-5f

typedef unsigned long long ull;

// ---------------- scratch (device globals; no allocation allowed) ----------------
__device__ unsigned int g_hb[MAXN * 128];   // [N][128] words; each word = 2 bf16.
                                            // layer1 = pairs 0..63, layer2 = pairs 64..127
__device__ float g_srcv[MAXN * 8];          // per-node src logits: es1[4] | es2[4]
__device__ float g_dstv[MAXN * 8];          // per-node dst logits: ed1[4] | ed2[4]
__device__ int   g_deg[MAXN];               // in-degree (incl self-loop)
__device__ int   g_off[MAXN + 1];           // CSR offsets
__device__ int   g_cursor[MAXN];            // scatter cursors
__device__ int   g_csr[MAXE + MAXN];        // CSR src indices (grouped by dst)
__device__ int   g_bsum[256];               // per-block degree sums
__device__ int   g_boff[256];               // exclusive block offsets

__device__ __forceinline__ float lrelu(float v) { return v > 0.f ? v : LRELU_SLOPE * v; }

__device__ __forceinline__ ull pack2(float x, float y) {
    ull r;
    asm("mov.b64 %0, {%1, %2};" : "=l"(r) : "f"(x), "f"(y));
    return r;
}
__device__ __forceinline__ void unpack2(ull v, float& x, float& y) {
    asm("mov.b64 {%0, %1}, %2;" : "=f"(x), "=f"(y) : "l"(v));
}
__device__ __forceinline__ void ffma2(ull& d, ull a, ull b) {
    asm("fma.rn.f32x2 %0, %1, %2, %0;" : "+l"(d) : "l"(a), "l"(b));
}
// pack two f32 into one word of two bf16 (lo -> low 16 bits, hi -> high 16 bits)
__device__ __forceinline__ unsigned int f2bf2(float lo, float hi) {
    unsigned int r;
    asm("cvt.rn.bf16x2.f32 %0, %1, %2;" : "=r"(r) : "f"(hi), "f"(lo));
    return r;
}
// word of two bf16 -> packed f32x2 (exact: bf16->f32 is <<16)
__device__ __forceinline__ ull bf2f2(unsigned int w) {
    ull r;
    asm("mov.b64 %0, {%1, %2};" : "=l"(r) : "r"(w << 16), "r"(w & 0xffff0000u));
    return r;
}
__device__ __forceinline__ float bflo(unsigned int w) { return __uint_as_float(w << 16); }
__device__ __forceinline__ float bfhi(unsigned int w) { return __uint_as_float(w & 0xffff0000u); }

// ---------------- kernel 1: h = x @ [W1 | W2]  (fp32 tiled GEMM, f32x2 FFMA, bf16 store) ----------------
#define BM 128
#define BN 128
#define BK 32
__global__ __launch_bounds__(256) void gemm_kernel(const float* __restrict__ x,
                                                   const float* __restrict__ W1,
                                                   const float* __restrict__ W2, int n) {
    __shared__ __align__(16) float Xs[BK][BM + 4];
    __shared__ __align__(16) float Ws[BK][BN];
    int tid = threadIdx.x;
    int rowBase = blockIdx.x * BM;
    const float* W = (blockIdx.y == 0) ? W1 : W2;
    int layerOff = blockIdx.y * 64;    // pair offset within g_hb row
    int tx = tid & 15, ty = tid >> 4;  // 16x16 thread grid, 8x8 micro-tile
    ull accp[8][4];
#pragma unroll
    for (int i = 0; i < 8; i++)
#pragma unroll
        for (int j = 0; j < 4; j++) accp[i][j] = 0ull;

    for (int k0 = 0; k0 < DIMV; k0 += BK) {
#pragma unroll
        for (int i = 0; i < 4; i++) {
            int idx = tid + i * 256;
            int r = idx >> 3;
            int c4 = idx & 7;
            int grow = rowBase + r;
            float4 v = make_float4(0.f, 0.f, 0.f, 0.f);
            if (grow < n) v = *(const float4*)&x[grow * DIMV + k0 + c4 * 4];
            Xs[c4 * 4 + 0][r] = v.x; Xs[c4 * 4 + 1][r] = v.y;
            Xs[c4 * 4 + 2][r] = v.z; Xs[c4 * 4 + 3][r] = v.w;
        }
#pragma unroll
        for (int i = 0; i < 4; i++) {
            int idx = tid + i * 256;
            int kr = idx >> 5;
            int c4 = idx & 31;
            *(float4*)&Ws[kr][c4 * 4] = *(const float4*)&W[(k0 + kr) * DIMV + c4 * 4];
        }
        __syncthreads();
#pragma unroll
        for (int kk = 0; kk < BK; kk++) {
            float a[8];
            *(float4*)&a[0] = *(const float4*)&Xs[kk][ty * 8];
            *(float4*)&a[4] = *(const float4*)&Xs[kk][ty * 8 + 4];
            longlong2 b01 = *(const longlong2*)&Ws[kk][tx * 8];
            longlong2 b23 = *(const longlong2*)&Ws[kk][tx * 8 + 4];
            ull bp0 = (ull)b01.x, bp1 = (ull)b01.y;
            ull bp2 = (ull)b23.x, bp3 = (ull)b23.y;
#pragma unroll
            for (int i = 0; i < 8; i++) {
                ull ap = pack2(a[i], a[i]);
                ffma2(accp[i][0], ap, bp0);
                ffma2(accp[i][1], ap, bp1);
                ffma2(accp[i][2], ap, bp2);
                ffma2(accp[i][3], ap, bp3);
            }
        }
        __syncthreads();
    }
#pragma unroll
    for (int i = 0; i < 8; i++) {
        int grow = rowBase + ty * 8 + i;
        if (grow >= n) continue;
        float c[8];
        unpack2(accp[i][0], c[0], c[1]);
        unpack2(accp[i][1], c[2], c[3]);
        unpack2(accp[i][2], c[4], c[5]);
        unpack2(accp[i][3], c[6], c[7]);
        uint4 pk;
        pk.x = f2bf2(c[0], c[1]);
        pk.y = f2bf2(c[2], c[3]);
        pk.z = f2bf2(c[4], c[5]);
        pk.w = f2bf2(c[6], c[7]);
        *(uint4*)&g_hb[grow * 128 + layerOff + tx * 4] = pk;
    }
}

// ---------------- kernel 2: per-node attention logits (warp per node) ----------------
__global__ void logits_kernel(const float* __restrict__ as1, const float* __restrict__ ad1,
                              const float* __restrict__ as2, const float* __restrict__ ad2, int n) {
    int warp = (blockIdx.x * blockDim.x + threadIdx.x) >> 5;
    if (warp >= n) return;
    int lane = threadIdx.x & 31;
    int head = lane >> 3;
    int sub = lane & 7;
    uint2 q1 = *(const uint2*)&g_hb[warp * 128 + lane * 2];
    uint2 q2 = *(const uint2*)&g_hb[warp * 128 + 64 + lane * 2];
    float4 h1 = make_float4(bflo(q1.x), bfhi(q1.x), bflo(q1.y), bfhi(q1.y));
    float4 h2 = make_float4(bflo(q2.x), bfhi(q2.x), bflo(q2.y), bfhi(q2.y));
    float4 v_s1 = *(const float4*)&as1[head * CH + sub * 4];
    float4 v_d1 = *(const float4*)&ad1[head * CH + sub * 4];
    float4 v_s2 = *(const float4*)&as2[head * CH + sub * 4];
    float4 v_d2 = *(const float4*)&ad2[head * CH + sub * 4];
    float ps1 = h1.x * v_s1.x + h1.y * v_s1.y + h1.z * v_s1.z + h1.w * v_s1.w;
    float pd1 = h1.x * v_d1.x + h1.y * v_d1.y + h1.z * v_d1.z + h1.w * v_d1.w;
    float ps2 = h2.x * v_s2.x + h2.y * v_s2.y + h2.z * v_s2.z + h2.w * v_s2.w;
    float pd2 = h2.x * v_d2.x + h2.y * v_d2.y + h2.z * v_d2.z + h2.w * v_d2.w;
#pragma unroll
    for (int off = 4; off; off >>= 1) {
        ps1 += __shfl_down_sync(0xffffffffu, ps1, off);
        pd1 += __shfl_down_sync(0xffffffffu, pd1, off);
        ps2 += __shfl_down_sync(0xffffffffu, ps2, off);
        pd2 += __shfl_down_sync(0xffffffffu, pd2, off);
    }
    if (sub == 0) {
        g_srcv[warp * 8 + head] = ps1;
        g_srcv[warp * 8 + 4 + head] = ps2;
        g_dstv[warp * 8 + head] = pd1;
        g_dstv[warp * 8 + 4 + head] = pd2;
    }
}

// ---------------- CSR build (all coalesced) ----------------
__global__ void init_deg_kernel(int n) {
    int i = blockIdx.x * blockDim.x + threadIdx.x;
    if (i < n) g_deg[i] = 1;   // self-loop
}

__global__ void count_kernel(const int* __restrict__ ei, int E) {
    int e = blockIdx.x * blockDim.x + threadIdx.x;
    if (e < E) atomicAdd(&g_deg[ei[E + e]], 1);
}

// Phase A: per-block (256-elem chunk) degree sum. Coalesced.
__global__ __launch_bounds__(256) void scanA_kernel(int n) {
    __shared__ int sm[8];
    int t = threadIdx.x;
    int i = blockIdx.x * 256 + t;
    int v = (i < n) ? g_deg[i] : 0;
#pragma unroll
    for (int off = 16; off; off >>= 1) v += __shfl_xor_sync(0xffffffffu, v, off);
    if ((t & 31) == 0) sm[t >> 5] = v;
    __syncthreads();
    if (t == 0) {
        int s = 0;
#pragma unroll
        for (int j = 0; j < 8; j++) s += sm[j];
        g_bsum[blockIdx.x] = s;
    }
}

// Phase B: single block scans the (<=256) block sums.
__global__ __launch_bounds__(256) void scanB_kernel(int nb, int n) {
    __shared__ int sm[256];
    int t = threadIdx.x;
    int v = (t < nb) ? g_bsum[t] : 0;
    sm[t] = v;
    __syncthreads();
#pragma unroll
    for (int off = 1; off < 256; off <<= 1) {
        int u = (t >= off) ? sm[t - off] : 0;
        __syncthreads();
        sm[t] += u;
        __syncthreads();
    }
    g_boff[t] = sm[t] - v;  // exclusive
    if (t == nb - 1) g_off[n] = sm[t];
}

// Phase C: per-block exclusive scan + CSR placement. Coalesced loads; csr writes ~monotone.
__global__ __launch_bounds__(256) void scanC_kernel(int n) {
    __shared__ int wsum[8];
    int t = threadIdx.x;
    int lane = t & 31, w = t >> 5;
    int i = blockIdx.x * 256 + t;
    int v = (i < n) ? g_deg[i] : 0;
    int x = v;
#pragma unroll
    for (int off = 1; off < 32; off <<= 1) {
        int u = __shfl_up_sync(0xffffffffu, x, off);
        if (lane >= off) x += u;
    }
    if (lane == 31) wsum[w] = x;
    __syncthreads();
    if (t == 0) {
        int acc = 0;
#pragma unroll
        for (int j = 0; j < 8; j++) { int tmp = wsum[j]; wsum[j] = acc; acc += tmp; }
    }
    __syncthreads();
    if (i < n) {
        int base = g_boff[blockIdx.x] + wsum[w] + (x - v);   // exclusive prefix
        g_off[i] = base;
        g_csr[base] = i;          // self-loop first
        g_cursor[i] = base + 1;
    }
}

__global__ void scatter_kernel(const int* __restrict__ ei, int E) {
    int e = blockIdx.x * blockDim.x + threadIdx.x;
    if (e >= E) return;
    int src = ei[e];
    int dst = ei[E + e];
    int pos = atomicAdd(&g_cursor[dst], 1);
    g_csr[pos] = src;
}

// ---------------- kernel 3: CSR aggregation + gate + residual + LN (warp per node) ----------------
__global__ __launch_bounds__(256) void agg_finalize_kernel(
        const float* __restrict__ x,
        const float* __restrict__ b1, const float* __restrict__ b2,
        const float* __restrict__ gW, const float* __restrict__ gb,
        const float* __restrict__ gamma, const float* __restrict__ beta,
        float* __restrict__ out, int n) {
    int node = (blockIdx.x * blockDim.x + threadIdx.x) >> 5;
    if (node >= n) return;
    int lane = threadIdx.x & 31;
    int head = lane >> 3;
    int c0 = lane * 4;

    float ed1 = g_dstv[node * 8 + head];
    float ed2 = g_dstv[node * 8 + 4 + head];
    int beg = g_off[node];
    int end = g_off[node + 1];

    ull num1a = 0ull, num1b = 0ull, num2a = 0ull, num2b = 0ull;
    float den1 = 0.f, den2 = 0.f;

    int s = __ldg(&g_csr[beg]);
    for (int p = beg; p < end; p++) {
        int s_next = (p + 1 < end) ? __ldg(&g_csr[p + 1]) : 0;
        float es1 = __ldg(&g_srcv[s * 8 + head]);
        float es2 = __ldg(&g_srcv[s * 8 + 4 + head]);
        uint2 q1 = *(const uint2*)&g_hb[s * 128 + lane * 2];
        uint2 q2 = *(const uint2*)&g_hb[s * 128 + 64 + lane * 2];
        float p1 = __expf(lrelu(es1 + ed1));
        float p2 = __expf(lrelu(es2 + ed2));
        den1 += p1; den2 += p2;
        ull p1p = pack2(p1, p1);
        ull p2p = pack2(p2, p2);
        ffma2(num1a, p1p, bf2f2(q1.x));
        ffma2(num1b, p1p, bf2f2(q1.y));
        ffma2(num2a, p2p, bf2f2(q2.x));
        ffma2(num2b, p2p, bf2f2(q2.y));
        s = s_next;
    }

    float inv1 = 1.f / den1;
    float inv2 = 1.f / den2;
    float4 num1, num2;
    unpack2(num1a, num1.x, num1.y); unpack2(num1b, num1.z, num1.w);
    unpack2(num2a, num2.x, num2.y); unpack2(num2b, num2.z, num2.w);
    float4 bb1 = *(const float4*)&b1[c0];
    float4 bb2 = *(const float4*)&b2[c0];
    float4 o1, o2;
    o1.x = num1.x * inv1 + bb1.x; o1.y = num1.y * inv1 + bb1.y;
    o1.z = num1.z * inv1 + bb1.z; o1.w = num1.w * inv1 + bb1.w;
    o2.x = num2.x * inv2 + bb2.x; o2.y = num2.y * inv2 + bb2.y;
    o2.z = num2.z * inv2 + bb2.z; o2.w = num2.w * inv2 + bb2.w;

    // gate logits: cat(out1,out2) @ gate_W[256,2]
    float g0 = 0.f, g1 = 0.f;
    {
        const float* w1r = &gW[c0 * 2];
        const float* w2r = &gW[(128 + c0) * 2];
        g0 += o1.x * w1r[0] + o1.y * w1r[2] + o1.z * w1r[4] + o1.w * w1r[6];
        g1 += o1.x * w1r[1] + o1.y * w1r[3] + o1.z * w1r[5] + o1.w * w1r[7];
        g0 += o2.x * w2r[0] + o2.y * w2r[2] + o2.z * w2r[4] + o2.w * w2r[6];
        g1 += o2.x * w2r[1] + o2.y * w2r[3] + o2.z * w2r[5] + o2.w * w2r[7];
    }
#pragma unroll
    for (int off = 16; off; off >>= 1) {
        g0 += __shfl_xor_sync(0xffffffffu, g0, off);
        g1 += __shfl_xor_sync(0xffffffffu, g1, off);
    }
    g0 += gb[0]; g1 += gb[1];
    float mx = fmaxf(g0, g1);
    float e0 = __expf(g0 - mx), e1 = __expf(g1 - mx);
    float inv_se = 1.f / (e0 + e1);
    float w0 = e0 * inv_se, w1 = e1 * inv_se;

    float4 xv = *(const float4*)&x[node * DIMV + c0];
    float4 y;
    y.x = xv.x + w0 * o1.x + w1 * o2.x;
    y.y = xv.y + w0 * o1.y + w1 * o2.y;
    y.z = xv.z + w0 * o1.z + w1 * o2.z;
    y.w = xv.w + w0 * o1.w + w1 * o2.w;
    float sum = y.x + y.y + y.z + y.w;
    float sq  = y.x * y.x + y.y * y.y + y.z * y.z + y.w * y.w;
#pragma unroll
    for (int off = 16; off; off >>= 1) {
        sum += __shfl_xor_sync(0xffffffffu, sum, off);
        sq  += __shfl_xor_sync(0xffffffffu, sq, off);
    }
    float mu = sum * (1.f / DIMV);
    float var = sq * (1.f / DIMV) - mu * mu;
    float inv = rsqrtf(var + LN_EPS);
    float4 gm = *(const float4*)&gamma[c0];
    float4 bt = *(const float4*)&beta[c0];
    float4 r;
    r.x = (y.x - mu) * inv * gm.x + bt.x;
    r.y = (y.y - mu) * inv * gm.y + bt.y;
    r.z = (y.z - mu) * inv * gm.z + bt.z;
    r.w = (y.w - mu) * inv * gm.w + bt.w;
    *(float4*)&out[node * DIMV + c0] = r;
}

// ---------------- launch ----------------
extern "C" void kernel_launch(void* const* d_in, const int* in_sizes, int n_in,
                              void* d_out, int out_size) {
    const float* x   = (const float*)d_in[0];
    const int*   ei  = (const int*)d_in[1];
    const float* W1  = (const float*)d_in[2];
    const float* b1  = (const float*)d_in[3];
    const float* as1 = (const float*)d_in[4];
    const float* ad1 = (const float*)d_in[5];
    const float* W2  = (const float*)d_in[6];
    const float* b2  = (const float*)d_in[7];
    const float* as2 = (const float*)d_in[8];
    const float* ad2 = (const float*)d_in[9];
    const float* gW  = (const float*)d_in[10];
    const float* gb  = (const float*)d_in[11];
    const float* gam = (const float*)d_in[12];
    const float* bet = (const float*)d_in[13];
    float* out = (float*)d_out;

    int n = in_sizes[0] / DIMV;       // nodes
    int E = in_sizes[1] / 2;          // edges (before self-loops)
    int nb = (n + 255) / 256;         // scan blocks (<= 256)

    // 1) h = x @ [W1 | W2], stored bf16
    {
        dim3 grid((n + BM - 1) / BM, 2);
        gemm_kernel<<<grid, 256>>>(x, W1, W2, n);
    }
    // 2) per-node logits
    logits_kernel<<<(n * 32 + 255) / 256, 256>>>(as1, ad1, as2, ad2, n);
    // 3) CSR build (dst-grouped), fully coalesced scan
    init_deg_kernel<<<(n + 255) / 256, 256>>>(n);
    count_kernel<<<(E + 255) / 256, 256>>>(ei, E);
    scanA_kernel<<<nb, 256>>>(n);
    scanB_kernel<<<1, 256>>>(nb, n);
    scanC_kernel<<<nb, 256>>>(n);
    scatter_kernel<<<(E + 255) / 256, 256>>>(ei, E);
    // 4) register-accumulated aggregation + gate + residual + LN
    agg_finalize_kernel<<<(n * 32 + 255) / 256, 256>>>(x, b1, b2, gW, gb, gam, bet, out, n);
}

// round 7
// speedup vs baseline: 1.7409x; 1.0235x over previous
#include <cuda_runtime.h>
#include <cuda_bf16.h>
#include <cstdint>

// Problem constants (fixed by the reference)
#define MAXN 50000
#define DIMV 128
#define HEADS 4
#define CH 32
#define MAXE 800000
#define LRELU_SLOPE 0.2f
#define LN_EPS 1e-5f

typedef unsigned long long ull;

// ---------------- scratch (device globals; no allocation allowed) ----------------
// g_hb layout: [N][128] words, word = 2 bf16. For pair p (0..63 channel pairs), layer l:
//   word = (p>>1)*4 + l*2 + (p&1)
// => lane's uint4 at word lane*4 holds {h1 pair 2lane, h1 pair 2lane+1, h2 pair 2lane, h2 pair 2lane+1}
__device__ unsigned int g_hb[MAXN * 128];
__device__ float g_srcv[MAXN * 8];          // [node][head][layer] : float2 per head
__device__ float g_dstv[MAXN * 8];          // same layout
__device__ int   g_deg[MAXN];               // in-degree (incl self-loop)
__device__ int   g_off[MAXN + 1];           // CSR offsets
__device__ int   g_cursor[MAXN];            // scatter cursors
__device__ int   g_csr[MAXE + MAXN];        // CSR src indices (grouped by dst)
__device__ int   g_bsum[256];               // per-block degree sums
__device__ int   g_boff[256];               // exclusive block offsets

__device__ __forceinline__ float lrelu(float v) { return v > 0.f ? v : LRELU_SLOPE * v; }

__device__ __forceinline__ ull pack2(float x, float y) {
    ull r;
    asm("mov.b64 %0, {%1, %2};" : "=l"(r) : "f"(x), "f"(y));
    return r;
}
__device__ __forceinline__ void unpack2(ull v, float& x, float& y) {
    asm("mov.b64 {%0, %1}, %2;" : "=f"(x), "=f"(y) : "l"(v));
}
__device__ __forceinline__ void ffma2(ull& d, ull a, ull b) {
    asm("fma.rn.f32x2 %0, %1, %2, %0;" : "+l"(d) : "l"(a), "l"(b));
}
// pack two f32 into one word of two bf16 (lo -> low 16 bits, hi -> high 16 bits)
__device__ __forceinline__ unsigned int f2bf2(float lo, float hi) {
    unsigned int r;
    asm("cvt.rn.bf16x2.f32 %0, %1, %2;" : "=r"(r) : "f"(hi), "f"(lo));
    return r;
}
// word of two bf16 -> packed f32x2 (exact: bf16->f32 is <<16)
__device__ __forceinline__ ull bf2f2(unsigned int w) {
    ull r;
    asm("mov.b64 %0, {%1, %2};" : "=l"(r) : "r"(w << 16), "r"(w & 0xffff0000u));
    return r;
}
__device__ __forceinline__ float bflo(unsigned int w) { return __uint_as_float(w << 16); }
__device__ __forceinline__ float bfhi(unsigned int w) { return __uint_as_float(w & 0xffff0000u); }

// ---------------- kernel 1: h = x @ [W1 | W2]  (fp32 tiled GEMM, f32x2 FFMA, bf16 store) ----------------
#define BM 128
#define BN 128
#define BK 32
__global__ __launch_bounds__(256) void gemm_kernel(const float* __restrict__ x,
                                                   const float* __restrict__ W1,
                                                   const float* __restrict__ W2, int n) {
    __shared__ __align__(16) float Xs[BK][BM + 4];
    __shared__ __align__(16) float Ws[BK][BN];
    int tid = threadIdx.x;
    int rowBase = blockIdx.x * BM;
    int l = blockIdx.y;                // layer 0 / 1
    const float* W = (l == 0) ? W1 : W2;
    int tx = tid & 15, ty = tid >> 4;  // 16x16 thread grid, 8x8 micro-tile
    ull accp[8][4];
#pragma unroll
    for (int i = 0; i < 8; i++)
#pragma unroll
        for (int j = 0; j < 4; j++) accp[i][j] = 0ull;

    for (int k0 = 0; k0 < DIMV; k0 += BK) {
#pragma unroll
        for (int i = 0; i < 4; i++) {
            int idx = tid + i * 256;
            int r = idx >> 3;
            int c4 = idx & 7;
            int grow = rowBase + r;
            float4 v = make_float4(0.f, 0.f, 0.f, 0.f);
            if (grow < n) v = *(const float4*)&x[grow * DIMV + k0 + c4 * 4];
            Xs[c4 * 4 + 0][r] = v.x; Xs[c4 * 4 + 1][r] = v.y;
            Xs[c4 * 4 + 2][r] = v.z; Xs[c4 * 4 + 3][r] = v.w;
        }
#pragma unroll
        for (int i = 0; i < 4; i++) {
            int idx = tid + i * 256;
            int kr = idx >> 5;
            int c4 = idx & 31;
            *(float4*)&Ws[kr][c4 * 4] = *(const float4*)&W[(k0 + kr) * DIMV + c4 * 4];
        }
        __syncthreads();
#pragma unroll
        for (int kk = 0; kk < BK; kk++) {
            float a[8];
            *(float4*)&a[0] = *(const float4*)&Xs[kk][ty * 8];
            *(float4*)&a[4] = *(const float4*)&Xs[kk][ty * 8 + 4];
            longlong2 b01 = *(const longlong2*)&Ws[kk][tx * 8];
            longlong2 b23 = *(const longlong2*)&Ws[kk][tx * 8 + 4];
            ull bp0 = (ull)b01.x, bp1 = (ull)b01.y;
            ull bp2 = (ull)b23.x, bp3 = (ull)b23.y;
#pragma unroll
            for (int i = 0; i < 8; i++) {
                ull ap = pack2(a[i], a[i]);
                ffma2(accp[i][0], ap, bp0);
                ffma2(accp[i][1], ap, bp1);
                ffma2(accp[i][2], ap, bp2);
                ffma2(accp[i][3], ap, bp3);
            }
        }
        __syncthreads();
    }
    // epilogue: channels tx*8..tx*8+7 = pairs 4tx..4tx+3, layer l
    // words: 8tx+2l, 8tx+2l+1 (pairs 4tx,4tx+1) and 8tx+4+2l, +1 (pairs 4tx+2,4tx+3)
#pragma unroll
    for (int i = 0; i < 8; i++) {
        int grow = rowBase + ty * 8 + i;
        if (grow >= n) continue;
        float c[8];
        unpack2(accp[i][0], c[0], c[1]);
        unpack2(accp[i][1], c[2], c[3]);
        unpack2(accp[i][2], c[4], c[5]);
        unpack2(accp[i][3], c[6], c[7]);
        uint2 pkA, pkB;
        pkA.x = f2bf2(c[0], c[1]);
        pkA.y = f2bf2(c[2], c[3]);
        pkB.x = f2bf2(c[4], c[5]);
        pkB.y = f2bf2(c[6], c[7]);
        *(uint2*)&g_hb[grow * 128 + 8 * tx + 2 * l]     = pkA;
        *(uint2*)&g_hb[grow * 128 + 8 * tx + 4 + 2 * l] = pkB;
    }
}

// ---------------- kernel 2: per-node attention logits (warp per node) + deg init ----------------
__global__ void logits_kernel(const float* __restrict__ as1, const float* __restrict__ ad1,
                              const float* __restrict__ as2, const float* __restrict__ ad2, int n) {
    int warp = (blockIdx.x * blockDim.x + threadIdx.x) >> 5;
    if (warp >= n) return;
    int lane = threadIdx.x & 31;
    int head = lane >> 3;
    int sub = lane & 7;
    if (lane == 0) g_deg[warp] = 1;   // self-loop degree init (fused)
    uint4 q = *(const uint4*)&g_hb[warp * 128 + lane * 4];
    float4 h1 = make_float4(bflo(q.x), bfhi(q.x), bflo(q.y), bfhi(q.y));
    float4 h2 = make_float4(bflo(q.z), bfhi(q.z), bflo(q.w), bfhi(q.w));
    float4 v_s1 = *(const float4*)&as1[head * CH + sub * 4];
    float4 v_d1 = *(const float4*)&ad1[head * CH + sub * 4];
    float4 v_s2 = *(const float4*)&as2[head * CH + sub * 4];
    float4 v_d2 = *(const float4*)&ad2[head * CH + sub * 4];
    float ps1 = h1.x * v_s1.x + h1.y * v_s1.y + h1.z * v_s1.z + h1.w * v_s1.w;
    float pd1 = h1.x * v_d1.x + h1.y * v_d1.y + h1.z * v_d1.z + h1.w * v_d1.w;
    float ps2 = h2.x * v_s2.x + h2.y * v_s2.y + h2.z * v_s2.z + h2.w * v_s2.w;
    float pd2 = h2.x * v_d2.x + h2.y * v_d2.y + h2.z * v_d2.z + h2.w * v_d2.w;
#pragma unroll
    for (int off = 4; off; off >>= 1) {
        ps1 += __shfl_down_sync(0xffffffffu, ps1, off);
        pd1 += __shfl_down_sync(0xffffffffu, pd1, off);
        ps2 += __shfl_down_sync(0xffffffffu, ps2, off);
        pd2 += __shfl_down_sync(0xffffffffu, pd2, off);
    }
    if (sub == 0) {
        // layout: [node][head][layer]
        g_srcv[warp * 8 + head * 2 + 0] = ps1;
        g_srcv[warp * 8 + head * 2 + 1] = ps2;
        g_dstv[warp * 8 + head * 2 + 0] = pd1;
        g_dstv[warp * 8 + head * 2 + 1] = pd2;
    }
}

// ---------------- CSR build (all coalesced) ----------------
__global__ void count_kernel(const int* __restrict__ ei, int E) {
    int e = blockIdx.x * blockDim.x + threadIdx.x;
    if (e < E) atomicAdd(&g_deg[ei[E + e]], 1);
}

__global__ __launch_bounds__(256) void scanA_kernel(int n) {
    __shared__ int sm[8];
    int t = threadIdx.x;
    int i = blockIdx.x * 256 + t;
    int v = (i < n) ? g_deg[i] : 0;
#pragma unroll
    for (int off = 16; off; off >>= 1) v += __shfl_xor_sync(0xffffffffu, v, off);
    if ((t & 31) == 0) sm[t >> 5] = v;
    __syncthreads();
    if (t == 0) {
        int s = 0;
#pragma unroll
        for (int j = 0; j < 8; j++) s += sm[j];
        g_bsum[blockIdx.x] = s;
    }
}

__global__ __launch_bounds__(256) void scanB_kernel(int nb, int n) {
    __shared__ int sm[256];
    int t = threadIdx.x;
    int v = (t < nb) ? g_bsum[t] : 0;
    sm[t] = v;
    __syncthreads();
#pragma unroll
    for (int off = 1; off < 256; off <<= 1) {
        int u = (t >= off) ? sm[t - off] : 0;
        __syncthreads();
        sm[t] += u;
        __syncthreads();
    }
    g_boff[t] = sm[t] - v;  // exclusive
    if (t == nb - 1) g_off[n] = sm[t];
}

__global__ __launch_bounds__(256) void scanC_kernel(int n) {
    __shared__ int wsum[8];
    int t = threadIdx.x;
    int lane = t & 31, w = t >> 5;
    int i = blockIdx.x * 256 + t;
    int v = (i < n) ? g_deg[i] : 0;
    int x = v;
#pragma unroll
    for (int off = 1; off < 32; off <<= 1) {
        int u = __shfl_up_sync(0xffffffffu, x, off);
        if (lane >= off) x += u;
    }
    if (lane == 31) wsum[w] = x;
    __syncthreads();
    if (t == 0) {
        int acc = 0;
#pragma unroll
        for (int j = 0; j < 8; j++) { int tmp = wsum[j]; wsum[j] = acc; acc += tmp; }
    }
    __syncthreads();
    if (i < n) {
        int base = g_boff[blockIdx.x] + wsum[w] + (x - v);   // exclusive prefix
        g_off[i] = base;
        g_csr[base] = i;          // self-loop first
        g_cursor[i] = base + 1;
    }
}

__global__ void scatter_kernel(const int* __restrict__ ei, int E) {
    int e = blockIdx.x * blockDim.x + threadIdx.x;
    if (e >= E) return;
    int src = ei[e];
    int dst = ei[E + e];
    int pos = atomicAdd(&g_cursor[dst], 1);
    g_csr[pos] = src;
}

// ---------------- kernel 3: CSR aggregation + gate + residual + LN (warp per node) ----------------
__global__ __launch_bounds__(256) void agg_finalize_kernel(
        const float* __restrict__ x,
        const float* __restrict__ b1, const float* __restrict__ b2,
        const float* __restrict__ gW, const float* __restrict__ gb,
        const float* __restrict__ gamma, const float* __restrict__ beta,
        float* __restrict__ out, int n) {
    int node = (blockIdx.x * blockDim.x + threadIdx.x) >> 5;
    if (node >= n) return;
    int lane = threadIdx.x & 31;
    int head = lane >> 3;
    int c0 = lane * 4;

    float2 ed = *(const float2*)&g_dstv[node * 8 + head * 2];  // (ed1, ed2)
    int beg = g_off[node];
    int end = g_off[node + 1];

    ull num1a = 0ull, num1b = 0ull, num2a = 0ull, num2b = 0ull;
    float den1 = 0.f, den2 = 0.f;

    int p = beg;
    // unrolled x2: two independent load/compute chains
    for (; p + 2 <= end; p += 2) {
        int sA = __ldg(&g_csr[p]);
        int sB = __ldg(&g_csr[p + 1]);
        float2 eA = *(const float2*)&g_srcv[sA * 8 + head * 2];
        float2 eB = *(const float2*)&g_srcv[sB * 8 + head * 2];
        uint4 qA = *(const uint4*)&g_hb[sA * 128 + lane * 4];
        uint4 qB = *(const uint4*)&g_hb[sB * 128 + lane * 4];
        float p1A = __expf(lrelu(eA.x + ed.x));
        float p2A = __expf(lrelu(eA.y + ed.y));
        float p1B = __expf(lrelu(eB.x + ed.x));
        float p2B = __expf(lrelu(eB.y + ed.y));
        den1 += p1A + p1B; den2 += p2A + p2B;
        ull p1Ap = pack2(p1A, p1A), p2Ap = pack2(p2A, p2A);
        ull p1Bp = pack2(p1B, p1B), p2Bp = pack2(p2B, p2B);
        ffma2(num1a, p1Ap, bf2f2(qA.x));
        ffma2(num1b, p1Ap, bf2f2(qA.y));
        ffma2(num2a, p2Ap, bf2f2(qA.z));
        ffma2(num2b, p2Ap, bf2f2(qA.w));
        ffma2(num1a, p1Bp, bf2f2(qB.x));
        ffma2(num1b, p1Bp, bf2f2(qB.y));
        ffma2(num2a, p2Bp, bf2f2(qB.z));
        ffma2(num2b, p2Bp, bf2f2(qB.w));
    }
    if (p < end) {
        int s = __ldg(&g_csr[p]);
        float2 eA = *(const float2*)&g_srcv[s * 8 + head * 2];
        uint4 q = *(const uint4*)&g_hb[s * 128 + lane * 4];
        float p1 = __expf(lrelu(eA.x + ed.x));
        float p2 = __expf(lrelu(eA.y + ed.y));
        den1 += p1; den2 += p2;
        ull p1p = pack2(p1, p1), p2p = pack2(p2, p2);
        ffma2(num1a, p1p, bf2f2(q.x));
        ffma2(num1b, p1p, bf2f2(q.y));
        ffma2(num2a, p2p, bf2f2(q.z));
        ffma2(num2b, p2p, bf2f2(q.w));
    }

    float inv1 = 1.f / den1;
    float inv2 = 1.f / den2;
    float4 num1, num2;
    unpack2(num1a, num1.x, num1.y); unpack2(num1b, num1.z, num1.w);
    unpack2(num2a, num2.x, num2.y); unpack2(num2b, num2.z, num2.w);
    float4 bb1 = *(const float4*)&b1[c0];
    float4 bb2 = *(const float4*)&b2[c0];
    float4 o1, o2;
    o1.x = num1.x * inv1 + bb1.x; o1.y = num1.y * inv1 + bb1.y;
    o1.z = num1.z * inv1 + bb1.z; o1.w = num1.w * inv1 + bb1.w;
    o2.x = num2.x * inv2 + bb2.x; o2.y = num2.y * inv2 + bb2.y;
    o2.z = num2.z * inv2 + bb2.z; o2.w = num2.w * inv2 + bb2.w;

    // gate logits: cat(out1,out2) @ gate_W[256,2]
    float g0 = 0.f, g1 = 0.f;
    {
        const float* w1r = &gW[c0 * 2];
        const float* w2r = &gW[(128 + c0) * 2];
        g0 += o1.x * w1r[0] + o1.y * w1r[2] + o1.z * w1r[4] + o1.w * w1r[6];
        g1 += o1.x * w1r[1] + o1.y * w1r[3] + o1.z * w1r[5] + o1.w * w1r[7];
        g0 += o2.x * w2r[0] + o2.y * w2r[2] + o2.z * w2r[4] + o2.w * w2r[6];
        g1 += o2.x * w2r[1] + o2.y * w2r[3] + o2.z * w2r[5] + o2.w * w2r[7];
    }
#pragma unroll
    for (int off = 16; off; off >>= 1) {
        g0 += __shfl_xor_sync(0xffffffffu, g0, off);
        g1 += __shfl_xor_sync(0xffffffffu, g1, off);
    }
    g0 += gb[0]; g1 += gb[1];
    float mx = fmaxf(g0, g1);
    float e0 = __expf(g0 - mx), e1 = __expf(g1 - mx);
    float inv_se = 1.f / (e0 + e1);
    float w0 = e0 * inv_se, w1 = e1 * inv_se;

    float4 xv = *(const float4*)&x[node * DIMV + c0];
    float4 y;
    y.x = xv.x + w0 * o1.x + w1 * o2.x;
    y.y = xv.y + w0 * o1.y + w1 * o2.y;
    y.z = xv.z + w0 * o1.z + w1 * o2.z;
    y.w = xv.w + w0 * o1.w + w1 * o2.w;
    float sum = y.x + y.y + y.z + y.w;
    float sq  = y.x * y.x + y.y * y.y + y.z * y.z + y.w * y.w;
#pragma unroll
    for (int off = 16; off; off >>= 1) {
        sum += __shfl_xor_sync(0xffffffffu, sum, off);
        sq  += __shfl_xor_sync(0xffffffffu, sq, off);
    }
    float mu = sum * (1.f / DIMV);
    float var = sq * (1.f / DIMV) - mu * mu;
    float inv = rsqrtf(var + LN_EPS);
    float4 gm = *(const float4*)&gamma[c0];
    float4 bt = *(const float4*)&beta[c0];
    float4 r;
    r.x = (y.x - mu) * inv * gm.x + bt.x;
    r.y = (y.y - mu) * inv * gm.y + bt.y;
    r.z = (y.z - mu) * inv * gm.z + bt.z;
    r.w = (y.w - mu) * inv * gm.w + bt.w;
    *(float4*)&out[node * DIMV + c0] = r;
}

// ---------------- launch ----------------
extern "C" void kernel_launch(void* const* d_in, const int* in_sizes, int n_in,
                              void* d_out, int out_size) {
    const float* x   = (const float*)d_in[0];
    const int*   ei  = (const int*)d_in[1];
    const float* W1  = (const float*)d_in[2];
    const float* b1  = (const float*)d_in[3];
    const float* as1 = (const float*)d_in[4];
    const float* ad1 = (const float*)d_in[5];
    const float* W2  = (const float*)d_in[6];
    const float* b2  = (const float*)d_in[7];
    const float* as2 = (const float*)d_in[8];
    const float* ad2 = (const float*)d_in[9];
    const float* gW  = (const float*)d_in[10];
    const float* gb  = (const float*)d_in[11];
    const float* gam = (const float*)d_in[12];
    const float* bet = (const float*)d_in[13];
    float* out = (float*)d_out;

    int n = in_sizes[0] / DIMV;       // nodes
    int E = in_sizes[1] / 2;          // edges (before self-loops)
    int nb = (n + 255) / 256;         // scan blocks (<= 256)

    // 1) h = x @ [W1 | W2], stored bf16 interleaved
    {
        dim3 grid((n + BM - 1) / BM, 2);
        gemm_kernel<<<grid, 256>>>(x, W1, W2, n);
    }
    // 2) per-node logits (+ deg=1 init)
    logits_kernel<<<(n * 32 + 255) / 256, 256>>>(as1, ad1, as2, ad2, n);
    // 3) CSR build (dst-grouped), fully coalesced scan
    count_kernel<<<(E + 255) / 256, 256>>>(ei, E);
    scanA_kernel<<<nb, 256>>>(n);
    scanB_kernel<<<1, 256>>>(nb, n);
    scanC_kernel<<<nb, 256>>>(n);
    scatter_kernel<<<(E + 255) / 256, 256>>>(ei, E);
    // 4) register-accumulated aggregation + gate + residual + LN
    agg_finalize_kernel<<<(n * 32 + 255) / 256, 256>>>(x, b1, b2, gW, gb, gam, bet, out, n);
}

// round 9
// speedup vs baseline: 1.8587x; 1.0677x over previous
#include <cuda_runtime.h>
#include <cuda_fp16.h>
#include <cuda_bf16.h>
#include <mma.h>
#include <cstdint>

using namespace nvcuda;

// Problem constants (fixed by the reference)
#define MAXN 50000
#define DIMV 128
#define HEADS 4
#define CH 32
#define MAXE 800000
#define LRELU_SLOPE 0.2f
#define LN_EPS 1e-5f

typedef unsigned long long ull;

// ---------------- scratch (device globals; no allocation allowed) ----------------
// g_hb layout: [N][128] words, word = 2 bf16. For channel-pair p (0..63), layer l:
//   word = (p>>1)*4 + l*2 + (p&1)
// => lane's uint4 at word lane*4 = {h1 pairs 2lane,2lane+1, h2 pairs 2lane,2lane+1}
__device__ unsigned int g_hb[MAXN * 128];
__device__ float g_srcv[MAXN * 8];          // [node][head][layer] : float2 per head
__device__ float g_dstv[MAXN * 8];          // same layout
__device__ int   g_deg[MAXN];               // in-degree (incl self-loop)
__device__ int   g_off[MAXN + 1];           // CSR offsets
__device__ int   g_cursor[MAXN];            // scatter cursors
__device__ int   g_csr[MAXE + MAXN];        // CSR src indices (grouped by dst)
__device__ int   g_bsum[256];               // per-block degree sums
__device__ int   g_boff[256];               // exclusive block offsets

__device__ __forceinline__ float lrelu(float v) { return v > 0.f ? v : LRELU_SLOPE * v; }

__device__ __forceinline__ ull pack2(float x, float y) {
    ull r;
    asm("mov.b64 %0, {%1, %2};" : "=l"(r) : "f"(x), "f"(y));
    return r;
}
__device__ __forceinline__ void unpack2(ull v, float& x, float& y) {
    asm("mov.b64 {%0, %1}, %2;" : "=f"(x), "=f"(y) : "l"(v));
}
__device__ __forceinline__ void ffma2(ull& d, ull a, ull b) {
    asm("fma.rn.f32x2 %0, %1, %2, %0;" : "+l"(d) : "l"(a), "l"(b));
}
__device__ __forceinline__ unsigned int f2bf2(float lo, float hi) {
    unsigned int r;
    asm("cvt.rn.bf16x2.f32 %0, %1, %2;" : "=r"(r) : "f"(hi), "f"(lo));
    return r;
}
// word of two bf16 -> packed f32x2 (exact: bf16->f32 is <<16)
__device__ __forceinline__ ull bf2f2(unsigned int w) {
    ull r;
    asm("mov.b64 %0, {%1, %2};" : "=l"(r) : "r"(w << 16), "r"(w & 0xffff0000u));
    return r;
}
__device__ __forceinline__ float bflo(unsigned int w) { return __uint_as_float(w << 16); }
__device__ __forceinline__ float bfhi(unsigned int w) { return __uint_as_float(w & 0xffff0000u); }

// ---------------- kernel 1: h = x @ [W1|W2] via HMMA (fp16 in, fp32 accum, bf16 out) ----------------
// grid: (ceil(n/64), 2 layers), block 256 (8 warps). Tile M=64, N=128, K=128 (2 chunks of 64).
#define XH_LD 72
#define WH_LD 136
#define CS_LD 132
#define GEMM_SMEM 33792   // max(64*72*2 + 64*136*2, 64*132*4) = max(26624, 33792)
__global__ __launch_bounds__(256) void gemm_hmma(const float* __restrict__ x,
                                                 const float* __restrict__ W1,
                                                 const float* __restrict__ W2, int n) {
    __shared__ __align__(16) char buf[GEMM_SMEM];
    half (*Xh)[XH_LD] = (half(*)[XH_LD])buf;                     // 64 x 72 half
    half (*Wh)[WH_LD] = (half(*)[WH_LD])(buf + 64 * XH_LD * 2);  // 64 x 136 half
    float (*Cs)[CS_LD] = (float(*)[CS_LD])buf;                   // 64 x 132 float (aliases Xh/Wh)

    int tid = threadIdx.x;
    int rowBase = blockIdx.x * 64;
    int l = blockIdx.y;
    const float* W = (l == 0) ? W1 : W2;
    int warp = tid >> 5;
    int wr = warp & 3;    // 4 row groups of 16
    int wc = warp >> 2;   // 2 col groups of 64

    wmma::fragment<wmma::accumulator, 16, 16, 16, float> acc[4];
#pragma unroll
    for (int j = 0; j < 4; j++) wmma::fill_fragment(acc[j], 0.f);

    int row4 = tid >> 2, q4 = tid & 3;   // 4 threads per row of 64
    for (int k0 = 0; k0 < DIMV; k0 += 64) {
        // load X tile 64x64 (fp32 -> half): 4 threads/row, 16 cols each
        {
            int grow = rowBase + row4;
#pragma unroll
            for (int i = 0; i < 4; i++) {
                float4 v = make_float4(0.f, 0.f, 0.f, 0.f);
                if (grow < n) v = *(const float4*)&x[grow * DIMV + k0 + q4 * 16 + i * 4];
                half2* dst = (half2*)&Xh[row4][q4 * 16 + i * 4];
                dst[0] = __floats2half2_rn(v.x, v.y);
                dst[1] = __floats2half2_rn(v.z, v.w);
            }
        }
        // load W tile 64x128 (fp32 -> half): 4 threads/row, 32 cols each
        {
#pragma unroll
            for (int i = 0; i < 8; i++) {
                float4 v = *(const float4*)&W[(k0 + row4) * DIMV + q4 * 32 + i * 4];
                half2* dst = (half2*)&Wh[row4][q4 * 32 + i * 4];
                dst[0] = __floats2half2_rn(v.x, v.y);
                dst[1] = __floats2half2_rn(v.z, v.w);
            }
        }
        __syncthreads();
#pragma unroll
        for (int kk = 0; kk < 4; kk++) {
            wmma::fragment<wmma::matrix_a, 16, 16, 16, half, wmma::row_major> fa;
            wmma::load_matrix_sync(fa, &Xh[wr * 16][kk * 16], XH_LD);
#pragma unroll
            for (int j = 0; j < 4; j++) {
                wmma::fragment<wmma::matrix_b, 16, 16, 16, half, wmma::row_major> fb;
                wmma::load_matrix_sync(fb, &Wh[kk * 16][wc * 64 + j * 16], WH_LD);
                wmma::mma_sync(acc[j], fa, fb, acc[j]);
            }
        }
        __syncthreads();
    }
    // stage C through smem, repack to interleaved bf16
#pragma unroll
    for (int j = 0; j < 4; j++)
        wmma::store_matrix_sync(&Cs[wr * 16][wc * 64 + j * 16], acc[j], CS_LD, wmma::mem_row_major);
    __syncthreads();
    {
        int grow = rowBase + row4;
        if (grow < n) {
#pragma unroll
            for (int pp = 0; pp < 16; pp += 2) {
                int p = 16 * q4 + pp;           // even channel-pair index
                float c0 = Cs[row4][2 * p + 0];
                float c1 = Cs[row4][2 * p + 1];
                float c2 = Cs[row4][2 * p + 2];
                float c3 = Cs[row4][2 * p + 3];
                uint2 w2;
                w2.x = f2bf2(c0, c1);
                w2.y = f2bf2(c2, c3);
                *(uint2*)&g_hb[grow * 128 + (p >> 1) * 4 + 2 * l] = w2;
            }
        }
    }
}

// ---------------- kernel 2: per-node attention logits (warp per node) + deg init ----------------
__global__ void logits_kernel(const float* __restrict__ as1, const float* __restrict__ ad1,
                              const float* __restrict__ as2, const float* __restrict__ ad2, int n) {
    int warp = (blockIdx.x * blockDim.x + threadIdx.x) >> 5;
    if (warp >= n) return;
    int lane = threadIdx.x & 31;
    int head = lane >> 3;
    int sub = lane & 7;
    if (lane == 0) g_deg[warp] = 1;   // self-loop degree init (fused)
    uint4 q = *(const uint4*)&g_hb[warp * 128 + lane * 4];
    float4 h1 = make_float4(bflo(q.x), bfhi(q.x), bflo(q.y), bfhi(q.y));
    float4 h2 = make_float4(bflo(q.z), bfhi(q.z), bflo(q.w), bfhi(q.w));
    float4 v_s1 = *(const float4*)&as1[head * CH + sub * 4];
    float4 v_d1 = *(const float4*)&ad1[head * CH + sub * 4];
    float4 v_s2 = *(const float4*)&as2[head * CH + sub * 4];
    float4 v_d2 = *(const float4*)&ad2[head * CH + sub * 4];
    float ps1 = h1.x * v_s1.x + h1.y * v_s1.y + h1.z * v_s1.z + h1.w * v_s1.w;
    float pd1 = h1.x * v_d1.x + h1.y * v_d1.y + h1.z * v_d1.z + h1.w * v_d1.w;
    float ps2 = h2.x * v_s2.x + h2.y * v_s2.y + h2.z * v_s2.z + h2.w * v_s2.w;
    float pd2 = h2.x * v_d2.x + h2.y * v_d2.y + h2.z * v_d2.z + h2.w * v_d2.w;
#pragma unroll
    for (int off = 4; off; off >>= 1) {
        ps1 += __shfl_down_sync(0xffffffffu, ps1, off);
        pd1 += __shfl_down_sync(0xffffffffu, pd1, off);
        ps2 += __shfl_down_sync(0xffffffffu, ps2, off);
        pd2 += __shfl_down_sync(0xffffffffu, pd2, off);
    }
    if (sub == 0) {
        g_srcv[warp * 8 + head * 2 + 0] = ps1;
        g_srcv[warp * 8 + head * 2 + 1] = ps2;
        g_dstv[warp * 8 + head * 2 + 0] = pd1;
        g_dstv[warp * 8 + head * 2 + 1] = pd2;
    }
}

// ---------------- CSR build ----------------
__global__ void count_kernel(const int* __restrict__ ei, int E) {
    int e4 = blockIdx.x * blockDim.x + threadIdx.x;
    int base = e4 * 4;
    if (base + 4 <= E && (E & 3) == 0) {
        int4 d = *(const int4*)&ei[E + base];
        atomicAdd(&g_deg[d.x], 1);
        atomicAdd(&g_deg[d.y], 1);
        atomicAdd(&g_deg[d.z], 1);
        atomicAdd(&g_deg[d.w], 1);
    } else {
        for (int e = base; e < E && e < base + 4; e++) atomicAdd(&g_deg[ei[E + e]], 1);
    }
}

__global__ __launch_bounds__(256) void scanA_kernel(int n) {
    __shared__ int sm[8];
    int t = threadIdx.x;
    int i = blockIdx.x * 256 + t;
    int v = (i < n) ? g_deg[i] : 0;
#pragma unroll
    for (int off = 16; off; off >>= 1) v += __shfl_xor_sync(0xffffffffu, v, off);
    if ((t & 31) == 0) sm[t >> 5] = v;
    __syncthreads();
    if (t == 0) {
        int s = 0;
#pragma unroll
        for (int j = 0; j < 8; j++) s += sm[j];
        g_bsum[blockIdx.x] = s;
    }
}

__global__ __launch_bounds__(256) void scanB_kernel(int nb, int n) {
    __shared__ int sm[256];
    int t = threadIdx.x;
    int v = (t < nb) ? g_bsum[t] : 0;
    sm[t] = v;
    __syncthreads();
#pragma unroll
    for (int off = 1; off < 256; off <<= 1) {
        int u = (t >= off) ? sm[t - off] : 0;
        __syncthreads();
        sm[t] += u;
        __syncthreads();
    }
    g_boff[t] = sm[t] - v;  // exclusive
    if (t == nb - 1) g_off[n] = sm[t];
}

__global__ __launch_bounds__(256) void scanC_kernel(int n) {
    __shared__ int wsum[8];
    int t = threadIdx.x;
    int lane = t & 31, w = t >> 5;
    int i = blockIdx.x * 256 + t;
    int v = (i < n) ? g_deg[i] : 0;
    int x = v;
#pragma unroll
    for (int off = 1; off < 32; off <<= 1) {
        int u = __shfl_up_sync(0xffffffffu, x, off);
        if (lane >= off) x += u;
    }
    if (lane == 31) wsum[w] = x;
    __syncthreads();
    if (t == 0) {
        int acc = 0;
#pragma unroll
        for (int j = 0; j < 8; j++) { int tmp = wsum[j]; wsum[j] = acc; acc += tmp; }
    }
    __syncthreads();
    if (i < n) {
        int base = g_boff[blockIdx.x] + wsum[w] + (x - v);   // exclusive prefix
        g_off[i] = base;
        g_csr[base] = i;          // self-loop first
        g_cursor[i] = base + 1;
    }
}

__global__ void scatter_kernel(const int* __restrict__ ei, int E) {
    int e4 = blockIdx.x * blockDim.x + threadIdx.x;
    int base = e4 * 4;
    if (base + 4 <= E && (E & 3) == 0) {
        int4 s = *(const int4*)&ei[base];
        int4 d = *(const int4*)&ei[E + base];
        g_csr[atomicAdd(&g_cursor[d.x], 1)] = s.x;
        g_csr[atomicAdd(&g_cursor[d.y], 1)] = s.y;
        g_csr[atomicAdd(&g_cursor[d.z], 1)] = s.z;
        g_csr[atomicAdd(&g_cursor[d.w], 1)] = s.w;
    } else {
        for (int e = base; e < E && e < base + 4; e++)
            g_csr[atomicAdd(&g_cursor[ei[E + e]], 1)] = ei[e];
    }
}

// ---------------- kernel 3: CSR aggregation + gate + residual + LN (warp per node) ----------------
__global__ __launch_bounds__(256) void agg_finalize_kernel(
        const float* __restrict__ x,
        const float* __restrict__ b1, const float* __restrict__ b2,
        const float* __restrict__ gW, const float* __restrict__ gb,
        const float* __restrict__ gamma, const float* __restrict__ beta,
        float* __restrict__ out, int n) {
    int node = (blockIdx.x * blockDim.x + threadIdx.x) >> 5;
    if (node >= n) return;
    int lane = threadIdx.x & 31;
    int head = lane >> 3;
    int c0 = lane * 4;
    const unsigned FULL = 0xffffffffu;

    float2 ed = *(const float2*)&g_dstv[node * 8 + head * 2];  // (ed1, ed2)
    int beg = g_off[node];
    int end = g_off[node + 1];

    ull num1a = 0ull, num1b = 0ull, num2a = 0ull, num2b = 0ull;
    float den1 = 0.f, den2 = 0.f;

#define AGG_STEP(e, q) {                                        \
        float p1 = __expf(lrelu((e).x + ed.x));                 \
        float p2 = __expf(lrelu((e).y + ed.y));                 \
        den1 += p1; den2 += p2;                                 \
        ull pa = pack2(p1, p1), pb = pack2(p2, p2);             \
        ffma2(num1a, pa, bf2f2((q).x));                         \
        ffma2(num1b, pa, bf2f2((q).y));                         \
        ffma2(num2a, pb, bf2f2((q).z));                         \
        ffma2(num2b, pb, bf2f2((q).w));                         \
    }

    int p = beg;
    // 4-edge chunks: one coalesced csr fetch + broadcast, then 4 independent load chains
    for (; p + 4 <= end; p += 4) {
        int idx = __ldg(&g_csr[p + (lane & 3)]);
        int s0 = __shfl_sync(FULL, idx, 0, 4);
        int s1 = __shfl_sync(FULL, idx, 1, 4);
        int s2 = __shfl_sync(FULL, idx, 2, 4);
        int s3 = __shfl_sync(FULL, idx, 3, 4);
        uint4 q0 = *(const uint4*)&g_hb[s0 * 128 + lane * 4];
        uint4 q1 = *(const uint4*)&g_hb[s1 * 128 + lane * 4];
        uint4 q2 = *(const uint4*)&g_hb[s2 * 128 + lane * 4];
        uint4 q3 = *(const uint4*)&g_hb[s3 * 128 + lane * 4];
        float2 e0 = *(const float2*)&g_srcv[s0 * 8 + head * 2];
        float2 e1 = *(const float2*)&g_srcv[s1 * 8 + head * 2];
        float2 e2 = *(const float2*)&g_srcv[s2 * 8 + head * 2];
        float2 e3 = *(const float2*)&g_srcv[s3 * 8 + head * 2];
        AGG_STEP(e0, q0)
        AGG_STEP(e1, q1)
        AGG_STEP(e2, q2)
        AGG_STEP(e3, q3)
    }
    for (; p < end; p++) {
        int s = __ldg(&g_csr[p]);
        uint4 q = *(const uint4*)&g_hb[s * 128 + lane * 4];
        float2 e = *(const float2*)&g_srcv[s * 8 + head * 2];
        AGG_STEP(e, q)
    }
#undef AGG_STEP

    float inv1 = 1.f / den1;
    float inv2 = 1.f / den2;
    float4 num1, num2;
    unpack2(num1a, num1.x, num1.y); unpack2(num1b, num1.z, num1.w);
    unpack2(num2a, num2.x, num2.y); unpack2(num2b, num2.z, num2.w);
    float4 bb1 = *(const float4*)&b1[c0];
    float4 bb2 = *(const float4*)&b2[c0];
    float4 o1, o2;
    o1.x = num1.x * inv1 + bb1.x; o1.y = num1.y * inv1 + bb1.y;
    o1.z = num1.z * inv1 + bb1.z; o1.w = num1.w * inv1 + bb1.w;
    o2.x = num2.x * inv2 + bb2.x; o2.y = num2.y * inv2 + bb2.y;
    o2.z = num2.z * inv2 + bb2.z; o2.w = num2.w * inv2 + bb2.w;

    // gate logits: cat(out1,out2) @ gate_W[256,2]
    float g0 = 0.f, g1 = 0.f;
    {
        const float* w1r = &gW[c0 * 2];
        const float* w2r = &gW[(128 + c0) * 2];
        g0 += o1.x * w1r[0] + o1.y * w1r[2] + o1.z * w1r[4] + o1.w * w1r[6];
        g1 += o1.x * w1r[1] + o1.y * w1r[3] + o1.z * w1r[5] + o1.w * w1r[7];
        g0 += o2.x * w2r[0] + o2.y * w2r[2] + o2.z * w2r[4] + o2.w * w2r[6];
        g1 += o2.x * w2r[1] + o2.y * w2r[3] + o2.z * w2r[5] + o2.w * w2r[7];
    }
#pragma unroll
    for (int off = 16; off; off >>= 1) {
        g0 += __shfl_xor_sync(0xffffffffu, g0, off);
        g1 += __shfl_xor_sync(0xffffffffu, g1, off);
    }
    g0 += gb[0]; g1 += gb[1];
    float mx = fmaxf(g0, g1);
    float e0 = __expf(g0 - mx), e1 = __expf(g1 - mx);
    float inv_se = 1.f / (e0 + e1);
    float w0 = e0 * inv_se, w1 = e1 * inv_se;

    float4 xv = *(const float4*)&x[node * DIMV + c0];
    float4 y;
    y.x = xv.x + w0 * o1.x + w1 * o2.x;
    y.y = xv.y + w0 * o1.y + w1 * o2.y;
    y.z = xv.z + w0 * o1.z + w1 * o2.z;
    y.w = xv.w + w0 * o1.w + w1 * o2.w;
    float sum = y.x + y.y + y.z + y.w;
    float sq  = y.x * y.x + y.y * y.y + y.z * y.z + y.w * y.w;
#pragma unroll
    for (int off = 16; off; off >>= 1) {
        sum += __shfl_xor_sync(0xffffffffu, sum, off);
        sq  += __shfl_xor_sync(0xffffffffu, sq, off);
    }
    float mu = sum * (1.f / DIMV);
    float var = sq * (1.f / DIMV) - mu * mu;
    float inv = rsqrtf(var + LN_EPS);
    float4 gm = *(const float4*)&gamma[c0];
    float4 bt = *(const float4*)&beta[c0];
    float4 r;
    r.x = (y.x - mu) * inv * gm.x + bt.x;
    r.y = (y.y - mu) * inv * gm.y + bt.y;
    r.z = (y.z - mu) * inv * gm.z + bt.z;
    r.w = (y.w - mu) * inv * gm.w + bt.w;
    *(float4*)&out[node * DIMV + c0] = r;
}

// ---------------- launch ----------------
extern "C" void kernel_launch(void* const* d_in, const int* in_sizes, int n_in,
                              void* d_out, int out_size) {
    const float* x   = (const float*)d_in[0];
    const int*   ei  = (const int*)d_in[1];
    const float* W1  = (const float*)d_in[2];
    const float* b1  = (const float*)d_in[3];
    const float* as1 = (const float*)d_in[4];
    const float* ad1 = (const float*)d_in[5];
    const float* W2  = (const float*)d_in[6];
    const float* b2  = (const float*)d_in[7];
    const float* as2 = (const float*)d_in[8];
    const float* ad2 = (const float*)d_in[9];
    const float* gW  = (const float*)d_in[10];
    const float* gb  = (const float*)d_in[11];
    const float* gam = (const float*)d_in[12];
    const float* bet = (const float*)d_in[13];
    float* out = (float*)d_out;

    int n = in_sizes[0] / DIMV;       // nodes
    int E = in_sizes[1] / 2;          // edges (before self-loops)
    int nb = (n + 255) / 256;         // scan blocks (<= 256)
    int e4 = (E + 3) / 4;             // 4-edge work items

    // 1) h = x @ [W1 | W2] via HMMA, stored bf16 interleaved
    gemm_hmma<<<dim3((n + 63) / 64, 2), 256>>>(x, W1, W2, n);
    // 2) per-node logits (+ deg=1 init)
    logits_kernel<<<(n * 32 + 255) / 256, 256>>>(as1, ad1, as2, ad2, n);
    // 3) CSR build (dst-grouped), fully coalesced scan
    count_kernel<<<(e4 + 255) / 256, 256>>>(ei, E);
    scanA_kernel<<<nb, 256>>>(n);
    scanB_kernel<<<1, 256>>>(nb, n);
    scanC_kernel<<<nb, 256>>>(n);
    scatter_kernel<<<(e4 + 255) / 256, 256>>>(ei, E);
    // 4) register-accumulated aggregation + gate + residual + LN
    agg_finalize_kernel<<<(n * 32 + 255) / 256, 256>>>(x, b1, b2, gW, gb, gam, bet, out, n);
}